// round 13
// baseline (speedup 1.0000x reference)
#include <cuda_runtime.h>
#include <cuda_fp16.h>
#include <cstdint>
#include <math.h>

#define Bb     8
#define Cc     384
#define NN     4096
#define HEADS  8
#define HD     48
#define CN     (Cc*NN)
#define C3     1152
#define C6c    64
#define C2c    192
#define C4c    96

// ---------------- scratch (all intermediates fp16; small stats fp32) ----------
__device__ __align__(16) __half g_xh    [Bb*NN*Cc];
__device__ __align__(16) __half g_qkvh  [(size_t)Bb*NN*C3];
__device__ __align__(16) __half g_ath   [Bb*NN*Cc];
__device__ __align__(16) __half g_t1h   [Bb*NN*Cc];
__device__ __align__(16) __half g_convxh[Bb*NN*Cc];
__device__ __align__(16) __half g_chmaph[Bb*NN*Cc];
__device__ __align__(16) __half g_tth   [Bb*NN*C6c];
__device__ __align__(16) __half g_u1h   [Bb*NN*C6c];
__device__ __align__(16) __half g_u2h   [Bb*NN*C6c];
__device__ __align__(16) __half g_u3h   [Bb*NN*C6c];
__device__ __align__(16) __half g_sph   [Bb*NN*C2c];
__device__ __align__(16) __half g_gatedh[Bb*NN*128];   // K padded 96 -> 128
__device__ __align__(16) __half g_yh    [Bb*NN*Cc];
__device__ __align__(16) __half g_wbuf  [917504];
__device__ float g_sumsq[Bb*2*Cc];
__device__ float g_gram [Bb*HEADS*HD*HD];
__device__ float g_attn [Bb*HEADS*HD*HD];
__device__ float g_tmean[Bb*C6c];
__device__ float g_ci1v [Bb*C6c];
__device__ float g_cm   [Bb*Cc];

#define W_QKV   0
#define W_DW1   442368
#define W_CPIN  589824
#define W_CI2C  614400
#define W_CPOUT 618496
#define W_SPIN  643072
#define W_SPOUT 716800      // padded: Cc rows x 128
#define W_PROJ  765952

__device__ __forceinline__ uint32_t smem_u32(const void* p) {
    uint32_t a;
    asm("{ .reg .u64 t; cvta.to.shared.u64 t, %1; cvt.u32.u64 %0, t; }" : "=r"(a) : "l"(p));
    return a;
}
__device__ __forceinline__ void cpa16u(uint32_t dst, const __half* src) {
    asm volatile("cp.async.cg.shared.global [%0], [%1], 16;"
                 :: "r"(dst), "l"(__cvta_generic_to_global(src)) : "memory");
}
#define CP_COMMIT() asm volatile("cp.async.commit_group;" ::: "memory")
#define CP_WAIT1()  asm volatile("cp.async.wait_group 1;" ::: "memory")
#define CP_WAIT0()  asm volatile("cp.async.wait_group 0;" ::: "memory")

__device__ __forceinline__ void ldsm4(uint32_t* r, uint32_t addr) {
    asm volatile("ldmatrix.sync.aligned.m8n8.x4.shared.b16 {%0,%1,%2,%3}, [%4];"
        : "=r"(r[0]), "=r"(r[1]), "=r"(r[2]), "=r"(r[3]) : "r"(addr));
}
__device__ __forceinline__ void ldsm4t(uint32_t* r, uint32_t addr) {
    asm volatile("ldmatrix.sync.aligned.m8n8.x4.trans.shared.b16 {%0,%1,%2,%3}, [%4];"
        : "=r"(r[0]), "=r"(r[1]), "=r"(r[2]), "=r"(r[3]) : "r"(addr));
}
__device__ __forceinline__ void ldsm2(uint32_t* r, uint32_t addr) {
    asm volatile("ldmatrix.sync.aligned.m8n8.x2.shared.b16 {%0,%1}, [%2];"
        : "=r"(r[0]), "=r"(r[1]) : "r"(addr));
}
__device__ __forceinline__ void mma_f16(float* d, uint32_t a0, uint32_t a1,
                                        uint32_t a2, uint32_t a3,
                                        uint32_t b0, uint32_t b1) {
    asm volatile(
        "mma.sync.aligned.m16n8k16.row.col.f32.f16.f16.f32 "
        "{%0,%1,%2,%3}, {%4,%5,%6,%7}, {%8,%9}, {%0,%1,%2,%3};"
        : "+f"(d[0]), "+f"(d[1]), "+f"(d[2]), "+f"(d[3])
        : "r"(a0), "r"(a1), "r"(a2), "r"(a3), "r"(b0), "r"(b1));
}
__device__ __forceinline__ float sigf(float v) { return 1.f / (1.f + expf(-v)); }

// ---------------- 3-stage pipelined fp16 ldmatrix GEMM, BK=64 -------------------
#define RSH 72       // halves per smem row (144B): conflict-free ldmatrix
template<int NI>
__global__ __launch_bounds__(256, 2)
void mma_gemm(const __half* __restrict__ A, int lda, long long abatch,
              const __half* __restrict__ B, int ldb, long long bbatch,
              const float* __restrict__ bias, int biasRowMode,
              const __half* __restrict__ emul, const float* __restrict__ escale,
              float* __restrict__ ssq,
              const __half* __restrict__ cAt, const __half* __restrict__ cCh,
              const __half* __restrict__ cCv, const float* __restrict__ cCm,
              float* __restrict__ Outf, __half* __restrict__ Outh,
              int ldo, long long obatch, int K)
{
    constexpr int n_tile = NI * 32;
    constexpr uint32_t STAGEB = (128 + n_tile) * RSH * 2;
    extern __shared__ __half sh[];
    const uint32_t smBase = smem_u32(sh);

    const int tid  = threadIdx.x;
    const int wid  = tid >> 5, lane = tid & 31;
    const int g    = lane >> 2, tig = lane & 3;
    const int z    = blockIdx.z;
    const int arow0 = blockIdx.y * 128;
    const int brow0 = blockIdx.x * n_tile;
    const int wm = (wid & 1) * 64;
    const int wn = (wid >> 1) * (NI * 8);

    const __half* Ab = A + (size_t)z * abatch + (size_t)arow0 * lda;
    const __half* Bp = B + (size_t)z * bbatch + (size_t)brow0 * ldb;

    const __half* aSrc[4];  uint32_t aDst[4];
    #pragma unroll
    for (int i = 0; i < 4; i++) {
        int e = tid + i * 256;
        aSrc[i] = Ab + (size_t)(e >> 3) * lda + (e & 7) * 8;
        aDst[i] = ((e >> 3) * RSH + (e & 7) * 8) * 2;
    }
    const __half* bSrc[NI]; uint32_t bDst[NI];
    #pragma unroll
    for (int i = 0; i < NI; i++) {
        int e = tid + i * 256;
        bSrc[i] = Bp + (size_t)(e >> 3) * ldb + (e & 7) * 8;
        bDst[i] = (128 * RSH + (e >> 3) * RSH + (e & 7) * 8) * 2;
    }

    uint32_t aOff[4];
    #pragma unroll
    for (int mi = 0; mi < 4; mi++)
        aOff[mi] = (((wm + mi * 16 + (lane & 15)) * RSH) + (lane >> 4) * 8) * 2;
    uint32_t bPairOff[(NI + 1) / 2];
    #pragma unroll
    for (int np = 0; np < NI / 2; np++)
        bPairOff[np] = ((128 + wn + np * 16 + ((lane >> 4) << 3) + (lane & 7)) * RSH +
                        ((lane >> 3) & 1) * 8) * 2;
    uint32_t bSoloOff = ((128 + wn + (NI - 1) * 8 + (lane & 7)) * RSH +
                         ((lane >> 3) & 1) * 8) * 2;

    float c[4][NI][4];
    #pragma unroll
    for (int mi = 0; mi < 4; mi++)
        #pragma unroll
        for (int ni = 0; ni < NI; ni++)
            #pragma unroll
            for (int q = 0; q < 4; q++) c[mi][ni][q] = 0.f;

    auto loadTiles = [&](int kc, uint32_t stBase) {
        const int koff = kc * 64;
        #pragma unroll
        for (int i = 0; i < 4; i++)
            cpa16u(stBase + aDst[i], aSrc[i] + koff);
        #pragma unroll
        for (int i = 0; i < NI; i++)
            cpa16u(stBase + bDst[i], bSrc[i] + koff);
        CP_COMMIT();
    };

    const int nch = K >> 6;
    loadTiles(0, smBase);
    if (nch > 1) loadTiles(1, smBase + STAGEB); else CP_COMMIT();

    uint32_t smC = smBase;
    uint32_t smL = smBase + 2 * STAGEB;
    for (int kc = 0; kc < nch; kc++) {
        CP_WAIT1();
        __syncthreads();
        if (kc + 2 < nch) loadTiles(kc + 2, smL); else CP_COMMIT();

        #pragma unroll
        for (int ks = 0; ks < 4; ks++) {
            const uint32_t kb = ks * 32;
            uint32_t a[4][4];
            #pragma unroll
            for (int mi = 0; mi < 4; mi++)
                ldsm4(a[mi], smC + aOff[mi] + kb);
            uint32_t b[NI][2];
            #pragma unroll
            for (int np = 0; np < NI / 2; np++) {
                uint32_t r[4]; ldsm4(r, smC + bPairOff[np] + kb);
                b[2*np][0] = r[0]; b[2*np][1] = r[1];
                b[2*np+1][0] = r[2]; b[2*np+1][1] = r[3];
            }
            if (NI & 1) ldsm2(b[NI-1], smC + bSoloOff + kb);
            #pragma unroll
            for (int ni = 0; ni < NI; ni++)
                #pragma unroll
                for (int mi = 0; mi < 4; mi++)
                    mma_f16(c[mi][ni], a[mi][0], a[mi][1], a[mi][2], a[mi][3],
                            b[ni][0], b[ni][1]);
        }
        smC = (smC == smBase + 2 * STAGEB) ? smBase : smC + STAGEB;
        smL = (smL == smBase + 2 * STAGEB) ? smBase : smL + STAGEB;
    }

    if (ssq) {
        #pragma unroll
        for (int ni = 0; ni < NI; ni++) {
            int col = brow0 + wn + ni * 8 + tig * 2;
            if (col < 2 * Cc) {
                float s0 = 0.f, s1 = 0.f;
                #pragma unroll
                for (int mi = 0; mi < 4; mi++) {
                    s0 += c[mi][ni][0] * c[mi][ni][0] + c[mi][ni][2] * c[mi][ni][2];
                    s1 += c[mi][ni][1] * c[mi][ni][1] + c[mi][ni][3] * c[mi][ni][3];
                }
                s0 += __shfl_xor_sync(0xffffffffu, s0, 4);
                s1 += __shfl_xor_sync(0xffffffffu, s1, 4);
                s0 += __shfl_xor_sync(0xffffffffu, s0, 8);
                s1 += __shfl_xor_sync(0xffffffffu, s1, 8);
                s0 += __shfl_xor_sync(0xffffffffu, s0, 16);
                s1 += __shfl_xor_sync(0xffffffffu, s1, 16);
                if (g == 0) {
                    atomicAdd(&ssq[z * 2 * Cc + col], s0);
                    atomicAdd(&ssq[z * 2 * Cc + col + 1], s1);
                }
            }
        }
    }

    #pragma unroll
    for (int mi = 0; mi < 4; mi++) {
        const int row = arow0 + wm + mi * 16 + g;
        float bv0 = 0.f, bv1 = 0.f;
        if (bias && biasRowMode) { bv0 = bias[row]; bv1 = bias[row + 8]; }
        #pragma unroll
        for (int ni = 0; ni < NI; ni++) {
            const int col = brow0 + wn + ni * 8 + tig * 2;
            float bc0 = 0.f, bc1 = 0.f;
            if (bias && !biasRowMode) { bc0 = bias[col]; bc1 = bias[col + 1]; }
            size_t o0 = (size_t)z * obatch + (size_t)row * ldo + col;
            size_t o1 = o0 + 8 * (size_t)ldo;
            float v00 = c[mi][ni][0] + bv0 + bc0, v01 = c[mi][ni][1] + bv0 + bc1;
            float v10 = c[mi][ni][2] + bv1 + bc0, v11 = c[mi][ni][3] + bv1 + bc1;
            if (emul) {
                float2 m0 = __half22float2(*(const __half2*)(emul + o0));
                float2 m1 = __half22float2(*(const __half2*)(emul + o1));
                float s0 = escale[z * C6c + col], s1 = escale[z * C6c + col + 1];
                v00 *= m0.x * s0; v01 *= m0.y * s1;
                v10 *= m1.x * s0; v11 *= m1.y * s1;
            }
            if (cAt) {
                float sc0 = sigf(cCm[z * Cc + col] * (1.f / NN));
                float sc1 = sigf(cCm[z * Cc + col + 1] * (1.f / NN));
                float2 a0 = __half22float2(*(const __half2*)(cAt + o0));
                float2 a1 = __half22float2(*(const __half2*)(cAt + o1));
                float2 h0 = __half22float2(*(const __half2*)(cCh + o0));
                float2 h1 = __half22float2(*(const __half2*)(cCh + o1));
                float2 w0 = __half22float2(*(const __half2*)(cCv + o0));
                float2 w1 = __half22float2(*(const __half2*)(cCv + o1));
                v00 = (a0.x + h0.x) * sigf(v00) + w0.x * sc0;
                v01 = (a0.y + h0.y) * sigf(v01) + w0.y * sc1;
                v10 = (a1.x + h1.x) * sigf(v10) + w1.x * sc0;
                v11 = (a1.y + h1.y) * sigf(v11) + w1.y * sc1;
            }
            if (Outh) {
                *(__half2*)(Outh + o0) = __floats2half2_rn(v00, v01);
                *(__half2*)(Outh + o1) = __floats2half2_rn(v10, v11);
            } else {
                *(float2*)(Outf + o0) = make_float2(v00, v01);
                *(float2*)(Outf + o1) = make_float2(v10, v11);
            }
        }
    }
}

// ---------------- weight fp32 -> fp16 (entry may be K-padded) -------------------
struct WList { const float* s[8]; int n[8]; int off[8]; int padK[8]; int srcK[8]; };
__global__ void f2h_kernel(WList wl) {
    int idx = blockIdx.x * 256 + threadIdx.x;
    #pragma unroll
    for (int k = 0; k < 8; k++) {
        if (idx < wl.n[k]) {
            float v;
            if (wl.padK[k]) {
                int r = idx / wl.padK[k], kk = idx % wl.padK[k];
                v = (kk < wl.srcK[k]) ? wl.s[k][r * wl.srcK[k] + kk] : 0.f;
            } else v = wl.s[k][idx];
            g_wbuf[wl.off[k] + idx] = __float2half(v);
        }
    }
}

__global__ void zero_kernel() {
    int i = blockIdx.x * 256 + threadIdx.x;
    if (i < Bb*2*Cc)          g_sumsq[i] = 0.f;
    if (i < Bb*HEADS*HD*HD)   g_gram[i]  = 0.f;
    if (i < Bb*C6c)           g_tmean[i] = 0.f;
    if (i < Bb*Cc)            g_cm[i]    = 0.f;
    if (i < Bb*NN*4) {
        int row = i >> 2, seg = i & 3;
        *(uint4*)(g_gatedh + (size_t)row * 128 + 96 + seg * 8) = make_uint4(0,0,0,0);
    }
}

__global__ void transpose_kernel(const float* __restrict__ in) {
    __shared__ float t[32][33];
    int b = blockIdx.z, c0 = blockIdx.y * 32, n0 = blockIdx.x * 32;
    int tx = threadIdx.x, ty = threadIdx.y;
    for (int i = ty; i < 32; i += 8)
        t[i][tx] = in[(size_t)b * CN + (size_t)(c0 + i) * NN + n0 + tx];
    __syncthreads();
    for (int i = ty; i < 32; i += 8)
        g_xh[(size_t)b * CN + (size_t)(n0 + i) * Cc + c0 + tx] = __float2half(t[tx][i]);
}

// ---------------- MMA gram ------------------------------------------------------
__global__ __launch_bounds__(256) void gram_kernel() {
    int bh = blockIdx.y; int b = bh >> 3, h = bh & 7;
    int nbase = blockIdx.x * 1024;
    const __half* qp = g_qkvh + (size_t)b * NN * C3 + h * HD;
    const __half* kp = qp + Cc;
    __shared__ __align__(16) __half qs[128 * 56];
    __shared__ __align__(16) __half ks_[128 * 56];
    __shared__ float gsm[HD * HD];
    int tid = threadIdx.x, wid = tid >> 5, lane = tid & 31;
    int g = lane >> 2, t = lane & 3;
    for (int i = tid; i < HD * HD; i += 256) gsm[i] = 0.f;

    float c[3][6][4];
    #pragma unroll
    for (int mi = 0; mi < 3; mi++)
        #pragma unroll
        for (int nt = 0; nt < 6; nt++)
            #pragma unroll
            for (int q = 0; q < 4; q++) c[mi][nt][q] = 0.f;

    for (int ch = 0; ch < 8; ch++) {
        __syncthreads();
        for (int e = tid; e < 768; e += 256) {
            int r = e / 6, s = e % 6;
            size_t goff = (size_t)(nbase + ch * 128 + r) * C3 + s * 8;
            cpa16u(smem_u32(qs  + r * 56 + s * 8), qp + goff);
            cpa16u(smem_u32(ks_ + r * 56 + s * 8), kp + goff);
        }
        CP_COMMIT(); CP_WAIT0();
        __syncthreads();

        int nrow = wid * 16;
        uint32_t a[3][4], bb[6][2];
        #pragma unroll
        for (int mi = 0; mi < 3; mi++) {
            int row = nrow + (lane & 7) + ((lane >> 4) << 3);
            int col = mi * 16 + ((lane >> 3) & 1) * 8;
            ldsm4t(a[mi], smem_u32(qs) + (row * 56 + col) * 2);
        }
        #pragma unroll
        for (int p = 0; p < 3; p++) {
            int row = nrow + (lane & 7) + ((lane >> 3) & 1) * 8;
            int col = p * 16 + (lane >> 4) * 8;
            uint32_t r[4];
            ldsm4t(r, smem_u32(ks_) + (row * 56 + col) * 2);
            bb[2*p][0] = r[0]; bb[2*p][1] = r[1];
            bb[2*p+1][0] = r[2]; bb[2*p+1][1] = r[3];
        }
        #pragma unroll
        for (int mi = 0; mi < 3; mi++)
            #pragma unroll
            for (int nt = 0; nt < 6; nt++)
                mma_f16(c[mi][nt], a[mi][0], a[mi][1], a[mi][2], a[mi][3],
                        bb[nt][0], bb[nt][1]);
    }

    #pragma unroll
    for (int mi = 0; mi < 3; mi++)
        #pragma unroll
        for (int nt = 0; nt < 6; nt++)
            #pragma unroll
            for (int q = 0; q < 4; q++) {
                int i = mi * 16 + g + ((q & 2) ? 8 : 0);
                int j = nt * 8 + 2 * t + (q & 1);
                atomicAdd(&gsm[i * HD + j], c[mi][nt][q]);
            }
    __syncthreads();
    for (int i = tid; i < HD * HD; i += 256)
        atomicAdd(&g_gram[(size_t)bh * HD * HD + i], gsm[i]);
}

__global__ void softmax_kernel(const float* __restrict__ temp) {
    int gi = blockIdx.x;
    int i = gi % HD; int bh = gi / HD;
    int b = bh >> 3, h = bh & 7;
    int tid = threadIdx.x;
    float qi = rsqrtf(fmaxf(g_sumsq[b * 2 * Cc + h * HD + i], 1e-24f));
    float v = -3.4e38f;
    if (tid < HD) {
        float kj = rsqrtf(fmaxf(g_sumsq[b * 2 * Cc + Cc + h * HD + tid], 1e-24f));
        v = g_gram[(size_t)bh * HD * HD + i * HD + tid] * qi * kj * temp[h];
    }
    __shared__ float red[64];
    red[tid] = v; __syncthreads();
    for (int st = 32; st > 0; st >>= 1) {
        if (tid < st) red[tid] = fmaxf(red[tid], red[tid + st]);
        __syncthreads();
    }
    float m = red[0]; __syncthreads();
    float e = (tid < HD) ? expf(v - m) : 0.f;
    red[tid] = e; __syncthreads();
    for (int st = 32; st > 0; st >>= 1) {
        if (tid < st) red[tid] += red[tid + st];
        __syncthreads();
    }
    if (tid < HD) g_attn[(size_t)bh * HD * HD + i * HD + tid] = e / red[0];
}

__global__ __launch_bounds__(128) void attnv_kernel() {
    int bh = blockIdx.y; int b = bh >> 3, h = bh & 7;
    int n = blockIdx.x * 128 + threadIdx.x;
    __shared__ float sa[HD * HD];
    for (int e = threadIdx.x; e < HD * HD; e += 128)
        sa[e] = g_attn[(size_t)bh * HD * HD + e];
    __syncthreads();
    const __half* vp = g_qkvh + (size_t)(b * NN + n) * C3 + 2 * Cc + h * HD;
    float vr[HD];
    #pragma unroll
    for (int j6 = 0; j6 < 6; j6++) {
        uint4 u = ((const uint4*)vp)[j6];
        const __half2* hp = (const __half2*)&u;
        #pragma unroll
        for (int q = 0; q < 4; q++) {
            float2 f = __half22float2(hp[q]);
            vr[j6 * 8 + q * 2] = f.x; vr[j6 * 8 + q * 2 + 1] = f.y;
        }
    }
    __half* oph = g_ath + (size_t)(b * NN + n) * Cc + h * HD;
    #pragma unroll
    for (int i0 = 0; i0 < HD; i0 += 8) {
        float res[8];
        #pragma unroll
        for (int i = 0; i < 8; i++) {
            float s = 0.f;
            #pragma unroll
            for (int j = 0; j < HD; j++) s += sa[(i0 + i) * HD + j] * vr[j];
            res[i] = s;
        }
        __half2 hres[4];
        #pragma unroll
        for (int q = 0; q < 4; q++)
            hres[q] = __floats2half2_rn(res[q*2], res[q*2+1]);
        *(uint4*)(oph + i0) = *(uint4*)hres;
    }
}

// fp16-in fp16-out depthwise conv (NHWC, C % 4 == 0), fp32 accumulate
__global__ void dwconv4h(const __half* __restrict__ in, const float* __restrict__ w,
                         const float* __restrict__ bias, __half* __restrict__ out,
                         int C, int ks, int pad, int dil)
{
    int idx = blockIdx.x * 256 + threadIdx.x;
    int C4 = C >> 2;
    int c4 = idx % C4; int rest = idx / C4;
    int xx = rest & 63, yy = (rest >> 6) & 63, b = rest >> 12;
    int c = c4 << 2;
    const __half* ip = in + (size_t)(b * NN) * C + c;
    float4 bv = *(const float4*)(bias + c);
    float a0 = bv.x, a1 = bv.y, a2 = bv.z, a3 = bv.w;
    const float* wp = w + c * ks * ks;
    const int K2 = ks * ks;
    for (int ky = 0; ky < ks; ky++) {
        int y = yy - pad + ky * dil;
        if ((unsigned)y >= 64u) continue;
        for (int kx = 0; kx < ks; kx++) {
            int x = xx - pad + kx * dil;
            if ((unsigned)x >= 64u) continue;
            uint2 u = *(const uint2*)(ip + (size_t)(y * 64 + x) * C);
            const __half2* hp = (const __half2*)&u;
            float2 f0 = __half22float2(hp[0]), f1 = __half22float2(hp[1]);
            int t = ky * ks + kx;
            a0 += f0.x * wp[t];
            a1 += f0.y * wp[t + K2];
            a2 += f1.x * wp[t + 2 * K2];
            a3 += f1.y * wp[t + 3 * K2];
        }
    }
    __half2 hh[2] = {__floats2half2_rn(a0, a1), __floats2half2_rn(a2, a3)};
    *(uint2*)(out + (size_t)(b * NN + yy * 64 + xx) * C + c) = *(uint2*)hh;
}

// fused sp_dw (3x3 depthwise over C2c, fp16 in) + gelu gate -> gated (stride 128)
__global__ void spdw_gelu(const __half* __restrict__ sp, const float* __restrict__ w,
                          const float* __restrict__ bias, __half* __restrict__ out)
{
    int idx = blockIdx.x * 256 + threadIdx.x;
    int c4 = idx % 24; int rest = idx / 24;
    int xx = rest & 63, yy = (rest >> 6) & 63, b = rest >> 12;
    int c = c4 << 2;
    const __half* ip = sp + (size_t)(b * NN) * C2c;
    float4 bv1 = *(const float4*)(bias + c);
    float4 bv2 = *(const float4*)(bias + c + C4c);
    float a1[4] = {bv1.x, bv1.y, bv1.z, bv1.w};
    float a2[4] = {bv2.x, bv2.y, bv2.z, bv2.w};
    const float* w1 = w + c * 9;
    const float* w2 = w + (c + C4c) * 9;
    #pragma unroll
    for (int ky = 0; ky < 3; ky++) {
        int y = yy - 1 + ky;
        if ((unsigned)y >= 64u) continue;
        #pragma unroll
        for (int kx = 0; kx < 3; kx++) {
            int x = xx - 1 + kx;
            if ((unsigned)x >= 64u) continue;
            const __half* pv = ip + (size_t)(y * 64 + x) * C2c + c;
            uint2 u1v = *(const uint2*)pv;
            uint2 u2v = *(const uint2*)(pv + C4c);
            const __half2* h1 = (const __half2*)&u1v;
            const __half2* h2 = (const __half2*)&u2v;
            float2 f10 = __half22float2(h1[0]), f11 = __half22float2(h1[1]);
            float2 f20 = __half22float2(h2[0]), f21 = __half22float2(h2[1]);
            int t = ky * 3 + kx;
            a1[0] += f10.x * w1[t];      a1[1] += f10.y * w1[t + 9];
            a1[2] += f11.x * w1[t + 18]; a1[3] += f11.y * w1[t + 27];
            a2[0] += f20.x * w2[t];      a2[1] += f20.y * w2[t + 9];
            a2[2] += f21.x * w2[t + 18]; a2[3] += f21.y * w2[t + 27];
        }
    }
    float o[4];
    #pragma unroll
    for (int q = 0; q < 4; q++) {
        float gg = 0.5f * a1[q] * (1.f + erff(a1[q] * 0.70710678118654752f));
        o[q] = gg * a2[q];
    }
    __half2 hh[2] = {__floats2half2_rn(o[0], o[1]), __floats2half2_rn(o[2], o[3])};
    *(uint2*)(out + (size_t)(b * NN + yy * 64 + xx) * 128 + c) = *(uint2*)hh;
}

__global__ void tmean_kernel() {
    int b = blockIdx.y, n0 = blockIdx.x * 128, c = threadIdx.x;
    const __half* p = g_tth + (size_t)b * NN * C6c + c;
    float s = 0.f;
    for (int n = n0; n < n0 + 128; n++) s += __half2float(p[(size_t)n * C6c]);
    atomicAdd(&g_tmean[b * C6c + c], s);
}

__global__ void ci1_kernel(const float* __restrict__ w, const float* __restrict__ bias) {
    int b = blockIdx.x, co = threadIdx.x;
    __shared__ float tm[C6c];
    tm[co] = g_tmean[b * C6c + co] * (1.f / NN);
    __syncthreads();
    float a = bias[co];
    #pragma unroll
    for (int ci = 0; ci < C6c; ci++) a += w[co * C6c + ci] * tm[ci];
    g_ci1v[b * C6c + co] = a;
}

__global__ void cm_kernel() {
    int b = blockIdx.y, n0 = blockIdx.x * 128, c = threadIdx.x;
    const __half* p = g_chmaph + (size_t)b * NN * Cc + c;
    float s = 0.f;
    for (int n = n0; n < n0 + 128; n++) s += __half2float(p[(size_t)n * Cc]);
    atomicAdd(&g_cm[b * Cc + c], s);
}

// ================================================================= launch ===
extern "C" void kernel_launch(void* const* d_in, const int* in_sizes, int n_in,
                              void* d_out, int out_size)
{
    const float* x           = (const float*)d_in[0];
    const float* temperature = (const float*)d_in[1];
    const float* qkv_w       = (const float*)d_in[2];
    const float* proj_w      = (const float*)d_in[3];
    const float* proj_b      = (const float*)d_in[4];
    const float* dw1_w       = (const float*)d_in[5];
    const float* dw1_b       = (const float*)d_in[6];
    const float* dw2_w       = (const float*)d_in[7];
    const float* dw2_b       = (const float*)d_in[8];
    const float* cp_in_w     = (const float*)d_in[9];
    const float* cp_in_b     = (const float*)d_in[10];
    const float* ci1_w       = (const float*)d_in[11];
    const float* ci1_b       = (const float*)d_in[12];
    const float* ci2a_w      = (const float*)d_in[13];
    const float* ci2a_b      = (const float*)d_in[14];
    const float* ci2b_w      = (const float*)d_in[15];
    const float* ci2b_b      = (const float*)d_in[16];
    const float* ci2c_w      = (const float*)d_in[17];
    const float* ci2c_b      = (const float*)d_in[18];
    const float* cp_out_w    = (const float*)d_in[19];
    const float* cp_out_b    = (const float*)d_in[20];
    const float* sp_in_w     = (const float*)d_in[21];
    const float* sp_in_b     = (const float*)d_in[22];
    const float* sp_dw_w     = (const float*)d_in[23];
    const float* sp_dw_b     = (const float*)d_in[24];
    const float* sp_out_w    = (const float*)d_in[25];
    const float* sp_out_b    = (const float*)d_in[26];
    float* out = (float*)d_out;

    __half *xh, *qkvh, *ath, *t1h, *convxh, *chmaph, *tth, *u1h, *u2h,
           *u3h, *sph, *gatedh, *yh, *wb;
    float *ssq, *ci1v, *cm;
    cudaGetSymbolAddress((void**)&xh,     g_xh);
    cudaGetSymbolAddress((void**)&qkvh,   g_qkvh);
    cudaGetSymbolAddress((void**)&ath,    g_ath);
    cudaGetSymbolAddress((void**)&t1h,    g_t1h);
    cudaGetSymbolAddress((void**)&convxh, g_convxh);
    cudaGetSymbolAddress((void**)&chmaph, g_chmaph);
    cudaGetSymbolAddress((void**)&tth,    g_tth);
    cudaGetSymbolAddress((void**)&u1h,    g_u1h);
    cudaGetSymbolAddress((void**)&u2h,    g_u2h);
    cudaGetSymbolAddress((void**)&u3h,    g_u3h);
    cudaGetSymbolAddress((void**)&sph,    g_sph);
    cudaGetSymbolAddress((void**)&gatedh, g_gatedh);
    cudaGetSymbolAddress((void**)&yh,     g_yh);
    cudaGetSymbolAddress((void**)&wb,     g_wbuf);
    cudaGetSymbolAddress((void**)&ssq,    g_sumsq);
    cudaGetSymbolAddress((void**)&ci1v,   g_ci1v);
    cudaGetSymbolAddress((void**)&cm,     g_cm);

    const long long bCN  = CN;
    const long long b3CN = (long long)NN * C3;
    const long long b64  = (long long)NN * C6c;
    const long long b192 = (long long)NN * C2c;
    const long long b128 = (long long)NN * 128;

    const int SM4 = (128 + 128) * RSH * 2 * 3;   // 110592 B
    const int SM3 = (128 + 96)  * RSH * 2 * 3;   // 96768 B
    const int SM2 = (128 + 64)  * RSH * 2 * 3;   // 82944 B

    // one-time handles (created on the uncaptured correctness call)
    static bool inited = false;
    static cudaStream_t sB, sC;
    static cudaEvent_t evStart, evPro, evX, evQK, evV, evB, evCP, evC;
    if (!inited) {
        cudaStreamCreateWithFlags(&sB, cudaStreamNonBlocking);
        cudaStreamCreateWithFlags(&sC, cudaStreamNonBlocking);
        cudaEventCreateWithFlags(&evStart, cudaEventDisableTiming);
        cudaEventCreateWithFlags(&evPro,   cudaEventDisableTiming);
        cudaEventCreateWithFlags(&evX,     cudaEventDisableTiming);
        cudaEventCreateWithFlags(&evQK,    cudaEventDisableTiming);
        cudaEventCreateWithFlags(&evV,     cudaEventDisableTiming);
        cudaEventCreateWithFlags(&evB,     cudaEventDisableTiming);
        cudaEventCreateWithFlags(&evCP,    cudaEventDisableTiming);
        cudaEventCreateWithFlags(&evC,     cudaEventDisableTiming);
        cudaFuncSetAttribute(mma_gemm<4>, cudaFuncAttributeMaxDynamicSharedMemorySize, SM4);
        cudaFuncSetAttribute(mma_gemm<3>, cudaFuncAttributeMaxDynamicSharedMemorySize, SM3);
        cudaFuncSetAttribute(mma_gemm<2>, cudaFuncAttributeMaxDynamicSharedMemorySize, SM2);
        inited = true;
    }

    WList wl;
    for (int k = 0; k < 8; k++) { wl.padK[k] = 0; wl.srcK[k] = 0; }
    wl.s[0]=qkv_w;   wl.n[0]=3*Cc*Cc;  wl.off[0]=W_QKV;
    wl.s[1]=dw1_w;   wl.n[1]=Cc*Cc;    wl.off[1]=W_DW1;
    wl.s[2]=cp_in_w; wl.n[2]=C6c*Cc;   wl.off[2]=W_CPIN;
    wl.s[3]=ci2c_w;  wl.n[3]=C6c*C6c;  wl.off[3]=W_CI2C;
    wl.s[4]=cp_out_w;wl.n[4]=Cc*C6c;   wl.off[4]=W_CPOUT;
    wl.s[5]=sp_in_w; wl.n[5]=C2c*Cc;   wl.off[5]=W_SPIN;
    wl.s[6]=sp_out_w;wl.n[6]=Cc*128;   wl.off[6]=W_SPOUT; wl.padK[6]=128; wl.srcK[6]=96;
    wl.s[7]=proj_w;  wl.n[7]=Cc*Cc;    wl.off[7]=W_PROJ;

    // -------- prologue: f2h on sB concurrent with zero+transpose on main ----
    cudaEventRecord(evStart, 0);
    cudaStreamWaitEvent(sB, evStart, 0);
    f2h_kernel<<<1728, 256, 0, sB>>>(wl);
    cudaEventRecord(evPro, sB);
    zero_kernel<<<576, 256>>>();
    transpose_kernel<<<dim3(128, 12, Bb), dim3(32, 8)>>>(x);
    cudaEventRecord(evX, 0);
    cudaStreamWaitEvent(0, evPro, 0);          // main: weights ready
    cudaStreamWaitEvent(sB, evX, 0);           // sB: xh + zero ready

    // -------- QK-GEMM (768 cols) on main, V-GEMM (384 cols) on sB -----------
    mma_gemm<4><<<dim3(6, 32, Bb), 256, SM4>>>(xh, Cc, bCN, wb + W_QKV, Cc, 0,
        nullptr, 0, nullptr, nullptr, ssq, nullptr, nullptr, nullptr, nullptr,
        nullptr, qkvh, C3, b3CN, Cc);
    cudaEventRecord(evQK, 0);

    mma_gemm<4><<<dim3(3, 32, Bb), 256, SM4, sB>>>(xh, Cc, bCN,
        wb + W_QKV + 768 * Cc, Cc, 0, nullptr, 0, nullptr, nullptr, nullptr,
        nullptr, nullptr, nullptr, nullptr, nullptr, qkvh + 2 * Cc, C3, b3CN, Cc);
    cudaEventRecord(evV, sB);

    // -------- branch B (conv/spatial) continues on sB ------------------------
    mma_gemm<4><<<dim3(3, 32, Bb), 256, SM4, sB>>>(qkvh + 2 * Cc, C3, b3CN,
        wb + W_DW1, Cc, 0, dw1_b, 0, nullptr, nullptr, nullptr,
        nullptr, nullptr, nullptr, nullptr, nullptr, t1h, Cc, bCN, Cc);
    dwconv4h<<<(Bb * NN * Cc / 4) / 256, 256, 0, sB>>>(t1h, dw2_w, dw2_b, convxh, Cc, 3, 1, 1);
    mma_gemm<3><<<dim3(2, 32, Bb), 256, SM3, sB>>>(convxh, Cc, bCN, wb + W_SPIN, Cc, 0,
        sp_in_b, 0, nullptr, nullptr, nullptr, nullptr, nullptr, nullptr, nullptr,
        nullptr, sph, C2c, b192, Cc);
    spdw_gelu<<<(Bb * NN * 24) / 256, 256, 0, sB>>>(sph, sp_dw_w, sp_dw_b, gatedh);
    cudaEventRecord(evB, sB);

    // -------- branch A (attention/channel) on main stream -------------------
    gram_kernel<<<dim3(4, Bb * HEADS), 256>>>();
    softmax_kernel<<<Bb * HEADS * HD, 64>>>(temperature);
    cudaStreamWaitEvent(0, evV, 0);            // attnv needs v
    attnv_kernel<<<dim3(NN / 128, Bb * HEADS), 128>>>();
    mma_gemm<2><<<dim3(1, 32, Bb), 256, SM2>>>(ath, Cc, bCN, wb + W_CPIN, Cc, 0,
        cp_in_b, 0, nullptr, nullptr, nullptr, nullptr, nullptr, nullptr, nullptr,
        nullptr, tth, C6c, b64, Cc);
    cudaEventRecord(evCP, 0);
    // tmean + ci1 on sC, overlapped with ci2a/ci2b on main
    cudaStreamWaitEvent(sC, evCP, 0);
    tmean_kernel<<<dim3(32, Bb), 64, 0, sC>>>();
    ci1_kernel<<<Bb, C6c, 0, sC>>>(ci1_w, ci1_b);
    cudaEventRecord(evC, sC);
    dwconv4h<<<(Bb * NN * C6c / 4) / 256, 256>>>(tth, ci2a_w, ci2a_b, u1h, C6c, 3, 1, 1);
    dwconv4h<<<(Bb * NN * C6c / 4) / 256, 256>>>(u1h, ci2b_w, ci2b_b, u2h, C6c, 7, 9, 3);
    cudaStreamWaitEvent(0, evC, 0);
    mma_gemm<2><<<dim3(1, 32, Bb), 256, SM2>>>(u2h, C6c, b64, wb + W_CI2C, C6c, 0,
        ci2c_b, 0, tth, ci1v, nullptr, nullptr, nullptr, nullptr, nullptr,
        nullptr, u3h, C6c, b64, C6c);
    mma_gemm<4><<<dim3(3, 32, Bb), 256, SM4>>>(u3h, C6c, b64, wb + W_CPOUT, C6c, 0,
        cp_out_b, 0, nullptr, nullptr, nullptr, nullptr, nullptr, nullptr, nullptr,
        nullptr, chmaph, Cc, bCN, C6c);
    cm_kernel<<<dim3(32, Bb), Cc>>>();

    // -------- join, sp_out + fused combine, proj ----------------------------
    cudaStreamWaitEvent(0, evB, 0);
    mma_gemm<4><<<dim3(3, 32, Bb), 256, SM4>>>(gatedh, 128, b128, wb + W_SPOUT, 128, 0,
        sp_out_b, 0, nullptr, nullptr, nullptr, ath, chmaph, convxh, cm,
        nullptr, yh, Cc, bCN, 128);
    mma_gemm<4><<<dim3(32, 3, Bb), 256, SM4>>>(wb + W_PROJ, Cc, 0, yh, Cc, bCN,
        proj_b, 1, nullptr, nullptr, nullptr, nullptr, nullptr, nullptr, nullptr,
        out, nullptr, NN, bCN, Cc);
}

// round 14
// speedup vs baseline: 1.0667x; 1.0667x over previous
#include <cuda_runtime.h>
#include <cuda_fp16.h>
#include <cstdint>
#include <math.h>

#define Bb     8
#define Cc     384
#define NN     4096
#define HEADS  8
#define HD     48
#define CN     (Cc*NN)
#define C3     1152
#define C6c    64
#define C2c    192
#define C4c    96

// ---------------- scratch (all intermediates fp16; small stats fp32) ----------
__device__ __align__(16) __half g_xh    [Bb*NN*Cc];
__device__ __align__(16) __half g_qkvh  [(size_t)Bb*NN*C3];
__device__ __align__(16) __half g_ath   [Bb*NN*Cc];
__device__ __align__(16) __half g_t1h   [Bb*NN*Cc];
__device__ __align__(16) __half g_convxh[Bb*NN*Cc];
__device__ __align__(16) __half g_chmaph[Bb*NN*Cc];
__device__ __align__(16) __half g_tth   [Bb*NN*C6c];
__device__ __align__(16) __half g_u1h   [Bb*NN*C6c];
__device__ __align__(16) __half g_u2h   [Bb*NN*C6c];
__device__ __align__(16) __half g_u3h   [Bb*NN*C6c];
__device__ __align__(16) __half g_sph   [Bb*NN*C2c];
__device__ __align__(16) __half g_gatedh[Bb*NN*128];   // K padded 96 -> 128
__device__ __align__(16) __half g_yh    [Bb*NN*Cc];
__device__ __align__(16) __half g_wbuf  [917504];
__device__ float g_sumsq[Bb*2*Cc];
__device__ float g_gram [Bb*HEADS*HD*HD];
__device__ float g_attn [Bb*HEADS*HD*HD];
__device__ float g_tmean[Bb*C6c];
__device__ float g_ci1v [Bb*C6c];
__device__ float g_cm   [Bb*Cc];

#define W_QKV   0
#define W_DW1   442368
#define W_CPIN  589824
#define W_CI2C  614400
#define W_CPOUT 618496
#define W_SPIN  643072
#define W_SPOUT 716800      // padded: Cc rows x 128
#define W_PROJ  765952

__device__ __forceinline__ uint32_t smem_u32(const void* p) {
    uint32_t a;
    asm("{ .reg .u64 t; cvta.to.shared.u64 t, %1; cvt.u32.u64 %0, t; }" : "=r"(a) : "l"(p));
    return a;
}
__device__ __forceinline__ void cpa16u(uint32_t dst, const __half* src) {
    asm volatile("cp.async.cg.shared.global [%0], [%1], 16;"
                 :: "r"(dst), "l"(__cvta_generic_to_global(src)) : "memory");
}
#define CP_COMMIT() asm volatile("cp.async.commit_group;" ::: "memory")
#define CP_WAIT1()  asm volatile("cp.async.wait_group 1;" ::: "memory")
#define CP_WAIT0()  asm volatile("cp.async.wait_group 0;" ::: "memory")

__device__ __forceinline__ void ldsm4(uint32_t* r, uint32_t addr) {
    asm volatile("ldmatrix.sync.aligned.m8n8.x4.shared.b16 {%0,%1,%2,%3}, [%4];"
        : "=r"(r[0]), "=r"(r[1]), "=r"(r[2]), "=r"(r[3]) : "r"(addr));
}
__device__ __forceinline__ void ldsm4t(uint32_t* r, uint32_t addr) {
    asm volatile("ldmatrix.sync.aligned.m8n8.x4.trans.shared.b16 {%0,%1,%2,%3}, [%4];"
        : "=r"(r[0]), "=r"(r[1]), "=r"(r[2]), "=r"(r[3]) : "r"(addr));
}
__device__ __forceinline__ void ldsm2(uint32_t* r, uint32_t addr) {
    asm volatile("ldmatrix.sync.aligned.m8n8.x2.shared.b16 {%0,%1}, [%2];"
        : "=r"(r[0]), "=r"(r[1]) : "r"(addr));
}
__device__ __forceinline__ void mma_f16(float* d, uint32_t a0, uint32_t a1,
                                        uint32_t a2, uint32_t a3,
                                        uint32_t b0, uint32_t b1) {
    asm volatile(
        "mma.sync.aligned.m16n8k16.row.col.f32.f16.f16.f32 "
        "{%0,%1,%2,%3}, {%4,%5,%6,%7}, {%8,%9}, {%0,%1,%2,%3};"
        : "+f"(d[0]), "+f"(d[1]), "+f"(d[2]), "+f"(d[3])
        : "r"(a0), "r"(a1), "r"(a2), "r"(a3), "r"(b0), "r"(b1));
}
__device__ __forceinline__ float sigf(float v) { return 1.f / (1.f + expf(-v)); }

// ---------------- 3-stage pipelined fp16 ldmatrix GEMM, BK=64 -------------------
#define RSH 72       // halves per smem row (144B): conflict-free ldmatrix
template<int NI>
__global__ __launch_bounds__(256, 2)
void mma_gemm(const __half* __restrict__ A, int lda, long long abatch,
              const __half* __restrict__ B, int ldb, long long bbatch,
              const float* __restrict__ bias, int biasRowMode,
              const __half* __restrict__ emul, const float* __restrict__ escale,
              float* __restrict__ ssq,
              const __half* __restrict__ cAt, const __half* __restrict__ cCh,
              const __half* __restrict__ cCv, const float* __restrict__ cCm,
              float* __restrict__ Outf, __half* __restrict__ Outh,
              int ldo, long long obatch, int K)
{
    constexpr int n_tile = NI * 32;
    constexpr uint32_t STAGEB = (128 + n_tile) * RSH * 2;
    extern __shared__ __half sh[];
    const uint32_t smBase = smem_u32(sh);

    const int tid  = threadIdx.x;
    const int wid  = tid >> 5, lane = tid & 31;
    const int g    = lane >> 2, tig = lane & 3;
    const int z    = blockIdx.z;
    const int arow0 = blockIdx.y * 128;
    const int brow0 = blockIdx.x * n_tile;
    const int wm = (wid & 1) * 64;
    const int wn = (wid >> 1) * (NI * 8);

    const __half* Ab = A + (size_t)z * abatch + (size_t)arow0 * lda;
    const __half* Bp = B + (size_t)z * bbatch + (size_t)brow0 * ldb;

    const __half* aSrc[4];  uint32_t aDst[4];
    #pragma unroll
    for (int i = 0; i < 4; i++) {
        int e = tid + i * 256;
        aSrc[i] = Ab + (size_t)(e >> 3) * lda + (e & 7) * 8;
        aDst[i] = ((e >> 3) * RSH + (e & 7) * 8) * 2;
    }
    const __half* bSrc[NI]; uint32_t bDst[NI];
    #pragma unroll
    for (int i = 0; i < NI; i++) {
        int e = tid + i * 256;
        bSrc[i] = Bp + (size_t)(e >> 3) * ldb + (e & 7) * 8;
        bDst[i] = (128 * RSH + (e >> 3) * RSH + (e & 7) * 8) * 2;
    }

    uint32_t aOff[4];
    #pragma unroll
    for (int mi = 0; mi < 4; mi++)
        aOff[mi] = (((wm + mi * 16 + (lane & 15)) * RSH) + (lane >> 4) * 8) * 2;
    uint32_t bPairOff[(NI + 1) / 2];
    #pragma unroll
    for (int np = 0; np < NI / 2; np++)
        bPairOff[np] = ((128 + wn + np * 16 + ((lane >> 4) << 3) + (lane & 7)) * RSH +
                        ((lane >> 3) & 1) * 8) * 2;
    uint32_t bSoloOff = ((128 + wn + (NI - 1) * 8 + (lane & 7)) * RSH +
                         ((lane >> 3) & 1) * 8) * 2;

    float c[4][NI][4];
    #pragma unroll
    for (int mi = 0; mi < 4; mi++)
        #pragma unroll
        for (int ni = 0; ni < NI; ni++)
            #pragma unroll
            for (int q = 0; q < 4; q++) c[mi][ni][q] = 0.f;

    auto loadTiles = [&](int kc, uint32_t stBase) {
        const int koff = kc * 64;
        #pragma unroll
        for (int i = 0; i < 4; i++)
            cpa16u(stBase + aDst[i], aSrc[i] + koff);
        #pragma unroll
        for (int i = 0; i < NI; i++)
            cpa16u(stBase + bDst[i], bSrc[i] + koff);
        CP_COMMIT();
    };

    const int nch = K >> 6;
    loadTiles(0, smBase);
    if (nch > 1) loadTiles(1, smBase + STAGEB); else CP_COMMIT();

    uint32_t smC = smBase;
    uint32_t smL = smBase + 2 * STAGEB;
    for (int kc = 0; kc < nch; kc++) {
        CP_WAIT1();
        __syncthreads();
        if (kc + 2 < nch) loadTiles(kc + 2, smL); else CP_COMMIT();

        #pragma unroll
        for (int ks = 0; ks < 4; ks++) {
            const uint32_t kb = ks * 32;
            uint32_t a[4][4];
            #pragma unroll
            for (int mi = 0; mi < 4; mi++)
                ldsm4(a[mi], smC + aOff[mi] + kb);
            uint32_t b[NI][2];
            #pragma unroll
            for (int np = 0; np < NI / 2; np++) {
                uint32_t r[4]; ldsm4(r, smC + bPairOff[np] + kb);
                b[2*np][0] = r[0]; b[2*np][1] = r[1];
                b[2*np+1][0] = r[2]; b[2*np+1][1] = r[3];
            }
            if (NI & 1) ldsm2(b[NI-1], smC + bSoloOff + kb);
            #pragma unroll
            for (int ni = 0; ni < NI; ni++)
                #pragma unroll
                for (int mi = 0; mi < 4; mi++)
                    mma_f16(c[mi][ni], a[mi][0], a[mi][1], a[mi][2], a[mi][3],
                            b[ni][0], b[ni][1]);
        }
        smC = (smC == smBase + 2 * STAGEB) ? smBase : smC + STAGEB;
        smL = (smL == smBase + 2 * STAGEB) ? smBase : smL + STAGEB;
    }

    if (ssq) {
        #pragma unroll
        for (int ni = 0; ni < NI; ni++) {
            int col = brow0 + wn + ni * 8 + tig * 2;
            if (col < 2 * Cc) {
                float s0 = 0.f, s1 = 0.f;
                #pragma unroll
                for (int mi = 0; mi < 4; mi++) {
                    s0 += c[mi][ni][0] * c[mi][ni][0] + c[mi][ni][2] * c[mi][ni][2];
                    s1 += c[mi][ni][1] * c[mi][ni][1] + c[mi][ni][3] * c[mi][ni][3];
                }
                s0 += __shfl_xor_sync(0xffffffffu, s0, 4);
                s1 += __shfl_xor_sync(0xffffffffu, s1, 4);
                s0 += __shfl_xor_sync(0xffffffffu, s0, 8);
                s1 += __shfl_xor_sync(0xffffffffu, s1, 8);
                s0 += __shfl_xor_sync(0xffffffffu, s0, 16);
                s1 += __shfl_xor_sync(0xffffffffu, s1, 16);
                if (g == 0) {
                    atomicAdd(&ssq[z * 2 * Cc + col], s0);
                    atomicAdd(&ssq[z * 2 * Cc + col + 1], s1);
                }
            }
        }
    }

    #pragma unroll
    for (int mi = 0; mi < 4; mi++) {
        const int row = arow0 + wm + mi * 16 + g;
        float bv0 = 0.f, bv1 = 0.f;
        if (bias && biasRowMode) { bv0 = bias[row]; bv1 = bias[row + 8]; }
        #pragma unroll
        for (int ni = 0; ni < NI; ni++) {
            const int col = brow0 + wn + ni * 8 + tig * 2;
            float bc0 = 0.f, bc1 = 0.f;
            if (bias && !biasRowMode) { bc0 = bias[col]; bc1 = bias[col + 1]; }
            size_t o0 = (size_t)z * obatch + (size_t)row * ldo + col;
            size_t o1 = o0 + 8 * (size_t)ldo;
            float v00 = c[mi][ni][0] + bv0 + bc0, v01 = c[mi][ni][1] + bv0 + bc1;
            float v10 = c[mi][ni][2] + bv1 + bc0, v11 = c[mi][ni][3] + bv1 + bc1;
            if (emul) {
                float2 m0 = __half22float2(*(const __half2*)(emul + o0));
                float2 m1 = __half22float2(*(const __half2*)(emul + o1));
                float s0 = escale[z * C6c + col], s1 = escale[z * C6c + col + 1];
                v00 *= m0.x * s0; v01 *= m0.y * s1;
                v10 *= m1.x * s0; v11 *= m1.y * s1;
            }
            if (cAt) {
                float sc0 = sigf(cCm[z * Cc + col] * (1.f / NN));
                float sc1 = sigf(cCm[z * Cc + col + 1] * (1.f / NN));
                float2 a0 = __half22float2(*(const __half2*)(cAt + o0));
                float2 a1 = __half22float2(*(const __half2*)(cAt + o1));
                float2 h0 = __half22float2(*(const __half2*)(cCh + o0));
                float2 h1 = __half22float2(*(const __half2*)(cCh + o1));
                float2 w0 = __half22float2(*(const __half2*)(cCv + o0));
                float2 w1 = __half22float2(*(const __half2*)(cCv + o1));
                v00 = (a0.x + h0.x) * sigf(v00) + w0.x * sc0;
                v01 = (a0.y + h0.y) * sigf(v01) + w0.y * sc1;
                v10 = (a1.x + h1.x) * sigf(v10) + w1.x * sc0;
                v11 = (a1.y + h1.y) * sigf(v11) + w1.y * sc1;
            }
            if (Outh) {
                *(__half2*)(Outh + o0) = __floats2half2_rn(v00, v01);
                *(__half2*)(Outh + o1) = __floats2half2_rn(v10, v11);
            } else {
                *(float2*)(Outf + o0) = make_float2(v00, v01);
                *(float2*)(Outf + o1) = make_float2(v10, v11);
            }
        }
    }
}

// ---------------- weight fp32 -> fp16 (entry may be K-padded) -------------------
struct WList { const float* s[8]; int n[8]; int off[8]; int padK[8]; int srcK[8]; };
__global__ void f2h_kernel(WList wl) {
    int idx = blockIdx.x * 256 + threadIdx.x;
    #pragma unroll
    for (int k = 0; k < 8; k++) {
        if (idx < wl.n[k]) {
            float v;
            if (wl.padK[k]) {
                int r = idx / wl.padK[k], kk = idx % wl.padK[k];
                v = (kk < wl.srcK[k]) ? wl.s[k][r * wl.srcK[k] + kk] : 0.f;
            } else v = wl.s[k][idx];
            g_wbuf[wl.off[k] + idx] = __float2half(v);
        }
    }
}

__global__ void zero_kernel() {
    int i = blockIdx.x * 256 + threadIdx.x;
    if (i < Bb*2*Cc)          g_sumsq[i] = 0.f;
    if (i < Bb*HEADS*HD*HD)   g_gram[i]  = 0.f;
    if (i < Bb*C6c)           g_tmean[i] = 0.f;
    if (i < Bb*Cc)            g_cm[i]    = 0.f;
    if (i < Bb*NN*4) {
        int row = i >> 2, seg = i & 3;
        *(uint4*)(g_gatedh + (size_t)row * 128 + 96 + seg * 8) = make_uint4(0,0,0,0);
    }
}

__global__ void transpose_kernel(const float* __restrict__ in) {
    __shared__ float t[32][33];
    int b = blockIdx.z, c0 = blockIdx.y * 32, n0 = blockIdx.x * 32;
    int tx = threadIdx.x, ty = threadIdx.y;
    for (int i = ty; i < 32; i += 8)
        t[i][tx] = in[(size_t)b * CN + (size_t)(c0 + i) * NN + n0 + tx];
    __syncthreads();
    for (int i = ty; i < 32; i += 8)
        g_xh[(size_t)b * CN + (size_t)(n0 + i) * Cc + c0 + tx] = __float2half(t[tx][i]);
}

// ---------------- MMA gram ------------------------------------------------------
__global__ __launch_bounds__(256) void gram_kernel() {
    int bh = blockIdx.y; int b = bh >> 3, h = bh & 7;
    int nbase = blockIdx.x * 1024;
    const __half* qp = g_qkvh + (size_t)b * NN * C3 + h * HD;
    const __half* kp = qp + Cc;
    __shared__ __align__(16) __half qs[128 * 56];
    __shared__ __align__(16) __half ks_[128 * 56];
    __shared__ float gsm[HD * HD];
    int tid = threadIdx.x, wid = tid >> 5, lane = tid & 31;
    int g = lane >> 2, t = lane & 3;
    for (int i = tid; i < HD * HD; i += 256) gsm[i] = 0.f;

    float c[3][6][4];
    #pragma unroll
    for (int mi = 0; mi < 3; mi++)
        #pragma unroll
        for (int nt = 0; nt < 6; nt++)
            #pragma unroll
            for (int q = 0; q < 4; q++) c[mi][nt][q] = 0.f;

    for (int ch = 0; ch < 8; ch++) {
        __syncthreads();
        for (int e = tid; e < 768; e += 256) {
            int r = e / 6, s = e % 6;
            size_t goff = (size_t)(nbase + ch * 128 + r) * C3 + s * 8;
            cpa16u(smem_u32(qs  + r * 56 + s * 8), qp + goff);
            cpa16u(smem_u32(ks_ + r * 56 + s * 8), kp + goff);
        }
        CP_COMMIT(); CP_WAIT0();
        __syncthreads();

        int nrow = wid * 16;
        uint32_t a[3][4], bb[6][2];
        #pragma unroll
        for (int mi = 0; mi < 3; mi++) {
            int row = nrow + (lane & 7) + ((lane >> 4) << 3);
            int col = mi * 16 + ((lane >> 3) & 1) * 8;
            ldsm4t(a[mi], smem_u32(qs) + (row * 56 + col) * 2);
        }
        #pragma unroll
        for (int p = 0; p < 3; p++) {
            int row = nrow + (lane & 7) + ((lane >> 3) & 1) * 8;
            int col = p * 16 + (lane >> 4) * 8;
            uint32_t r[4];
            ldsm4t(r, smem_u32(ks_) + (row * 56 + col) * 2);
            bb[2*p][0] = r[0]; bb[2*p][1] = r[1];
            bb[2*p+1][0] = r[2]; bb[2*p+1][1] = r[3];
        }
        #pragma unroll
        for (int mi = 0; mi < 3; mi++)
            #pragma unroll
            for (int nt = 0; nt < 6; nt++)
                mma_f16(c[mi][nt], a[mi][0], a[mi][1], a[mi][2], a[mi][3],
                        bb[nt][0], bb[nt][1]);
    }

    #pragma unroll
    for (int mi = 0; mi < 3; mi++)
        #pragma unroll
        for (int nt = 0; nt < 6; nt++)
            #pragma unroll
            for (int q = 0; q < 4; q++) {
                int i = mi * 16 + g + ((q & 2) ? 8 : 0);
                int j = nt * 8 + 2 * t + (q & 1);
                atomicAdd(&gsm[i * HD + j], c[mi][nt][q]);
            }
    __syncthreads();
    for (int i = tid; i < HD * HD; i += 256)
        atomicAdd(&g_gram[(size_t)bh * HD * HD + i], gsm[i]);
}

__global__ void softmax_kernel(const float* __restrict__ temp) {
    int gi = blockIdx.x;
    int i = gi % HD; int bh = gi / HD;
    int b = bh >> 3, h = bh & 7;
    int tid = threadIdx.x;
    float qi = rsqrtf(fmaxf(g_sumsq[b * 2 * Cc + h * HD + i], 1e-24f));
    float v = -3.4e38f;
    if (tid < HD) {
        float kj = rsqrtf(fmaxf(g_sumsq[b * 2 * Cc + Cc + h * HD + tid], 1e-24f));
        v = g_gram[(size_t)bh * HD * HD + i * HD + tid] * qi * kj * temp[h];
    }
    __shared__ float red[64];
    red[tid] = v; __syncthreads();
    for (int st = 32; st > 0; st >>= 1) {
        if (tid < st) red[tid] = fmaxf(red[tid], red[tid + st]);
        __syncthreads();
    }
    float m = red[0]; __syncthreads();
    float e = (tid < HD) ? expf(v - m) : 0.f;
    red[tid] = e; __syncthreads();
    for (int st = 32; st > 0; st >>= 1) {
        if (tid < st) red[tid] += red[tid + st];
        __syncthreads();
    }
    if (tid < HD) g_attn[(size_t)bh * HD * HD + i * HD + tid] = e / red[0];
}

__global__ __launch_bounds__(128) void attnv_kernel() {
    int bh = blockIdx.y; int b = bh >> 3, h = bh & 7;
    int n = blockIdx.x * 128 + threadIdx.x;
    __shared__ float sa[HD * HD];
    for (int e = threadIdx.x; e < HD * HD; e += 128)
        sa[e] = g_attn[(size_t)bh * HD * HD + e];
    __syncthreads();
    const __half* vp = g_qkvh + (size_t)(b * NN + n) * C3 + 2 * Cc + h * HD;
    float vr[HD];
    #pragma unroll
    for (int j6 = 0; j6 < 6; j6++) {
        uint4 u = ((const uint4*)vp)[j6];
        const __half2* hp = (const __half2*)&u;
        #pragma unroll
        for (int q = 0; q < 4; q++) {
            float2 f = __half22float2(hp[q]);
            vr[j6 * 8 + q * 2] = f.x; vr[j6 * 8 + q * 2 + 1] = f.y;
        }
    }
    __half* oph = g_ath + (size_t)(b * NN + n) * Cc + h * HD;
    #pragma unroll
    for (int i0 = 0; i0 < HD; i0 += 8) {
        float res[8];
        #pragma unroll
        for (int i = 0; i < 8; i++) {
            float s = 0.f;
            #pragma unroll
            for (int j = 0; j < HD; j++) s += sa[(i0 + i) * HD + j] * vr[j];
            res[i] = s;
        }
        __half2 hres[4];
        #pragma unroll
        for (int q = 0; q < 4; q++)
            hres[q] = __floats2half2_rn(res[q*2], res[q*2+1]);
        *(uint4*)(oph + i0) = *(uint4*)hres;
    }
}

// fp16-in fp16-out depthwise conv (NHWC, C % 4 == 0), fp32 accumulate
__global__ void dwconv4h(const __half* __restrict__ in, const float* __restrict__ w,
                         const float* __restrict__ bias, __half* __restrict__ out,
                         int C, int ks, int pad, int dil)
{
    int idx = blockIdx.x * 256 + threadIdx.x;
    int C4 = C >> 2;
    int c4 = idx % C4; int rest = idx / C4;
    int xx = rest & 63, yy = (rest >> 6) & 63, b = rest >> 12;
    int c = c4 << 2;
    const __half* ip = in + (size_t)(b * NN) * C + c;
    float4 bv = *(const float4*)(bias + c);
    float a0 = bv.x, a1 = bv.y, a2 = bv.z, a3 = bv.w;
    const float* wp = w + c * ks * ks;
    const int K2 = ks * ks;
    for (int ky = 0; ky < ks; ky++) {
        int y = yy - pad + ky * dil;
        if ((unsigned)y >= 64u) continue;
        for (int kx = 0; kx < ks; kx++) {
            int x = xx - pad + kx * dil;
            if ((unsigned)x >= 64u) continue;
            uint2 u = *(const uint2*)(ip + (size_t)(y * 64 + x) * C);
            const __half2* hp = (const __half2*)&u;
            float2 f0 = __half22float2(hp[0]), f1 = __half22float2(hp[1]);
            int t = ky * ks + kx;
            a0 += f0.x * wp[t];
            a1 += f0.y * wp[t + K2];
            a2 += f1.x * wp[t + 2 * K2];
            a3 += f1.y * wp[t + 3 * K2];
        }
    }
    __half2 hh[2] = {__floats2half2_rn(a0, a1), __floats2half2_rn(a2, a3)};
    *(uint2*)(out + (size_t)(b * NN + yy * 64 + xx) * C + c) = *(uint2*)hh;
}

// fused sp_dw (3x3 depthwise over C2c, fp16 in) + gelu gate -> gated (stride 128)
__global__ void spdw_gelu(const __half* __restrict__ sp, const float* __restrict__ w,
                          const float* __restrict__ bias, __half* __restrict__ out)
{
    int idx = blockIdx.x * 256 + threadIdx.x;
    int c4 = idx % 24; int rest = idx / 24;
    int xx = rest & 63, yy = (rest >> 6) & 63, b = rest >> 12;
    int c = c4 << 2;
    const __half* ip = sp + (size_t)(b * NN) * C2c;
    float4 bv1 = *(const float4*)(bias + c);
    float4 bv2 = *(const float4*)(bias + c + C4c);
    float a1[4] = {bv1.x, bv1.y, bv1.z, bv1.w};
    float a2[4] = {bv2.x, bv2.y, bv2.z, bv2.w};
    const float* w1 = w + c * 9;
    const float* w2 = w + (c + C4c) * 9;
    #pragma unroll
    for (int ky = 0; ky < 3; ky++) {
        int y = yy - 1 + ky;
        if ((unsigned)y >= 64u) continue;
        #pragma unroll
        for (int kx = 0; kx < 3; kx++) {
            int x = xx - 1 + kx;
            if ((unsigned)x >= 64u) continue;
            const __half* pv = ip + (size_t)(y * 64 + x) * C2c + c;
            uint2 u1v = *(const uint2*)pv;
            uint2 u2v = *(const uint2*)(pv + C4c);
            const __half2* h1 = (const __half2*)&u1v;
            const __half2* h2 = (const __half2*)&u2v;
            float2 f10 = __half22float2(h1[0]), f11 = __half22float2(h1[1]);
            float2 f20 = __half22float2(h2[0]), f21 = __half22float2(h2[1]);
            int t = ky * 3 + kx;
            a1[0] += f10.x * w1[t];      a1[1] += f10.y * w1[t + 9];
            a1[2] += f11.x * w1[t + 18]; a1[3] += f11.y * w1[t + 27];
            a2[0] += f20.x * w2[t];      a2[1] += f20.y * w2[t + 9];
            a2[2] += f21.x * w2[t + 18]; a2[3] += f21.y * w2[t + 27];
        }
    }
    float o[4];
    #pragma unroll
    for (int q = 0; q < 4; q++) {
        float gg = 0.5f * a1[q] * (1.f + erff(a1[q] * 0.70710678118654752f));
        o[q] = gg * a2[q];
    }
    __half2 hh[2] = {__floats2half2_rn(o[0], o[1]), __floats2half2_rn(o[2], o[3])};
    *(uint2*)(out + (size_t)(b * NN + yy * 64 + xx) * 128 + c) = *(uint2*)hh;
}

__global__ void tmean_kernel() {
    int b = blockIdx.y, n0 = blockIdx.x * 128, c = threadIdx.x;
    const __half* p = g_tth + (size_t)b * NN * C6c + c;
    float s = 0.f;
    for (int n = n0; n < n0 + 128; n++) s += __half2float(p[(size_t)n * C6c]);
    atomicAdd(&g_tmean[b * C6c + c], s);
}

__global__ void ci1_kernel(const float* __restrict__ w, const float* __restrict__ bias) {
    int b = blockIdx.x, co = threadIdx.x;
    __shared__ float tm[C6c];
    tm[co] = g_tmean[b * C6c + co] * (1.f / NN);
    __syncthreads();
    float a = bias[co];
    #pragma unroll
    for (int ci = 0; ci < C6c; ci++) a += w[co * C6c + ci] * tm[ci];
    g_ci1v[b * C6c + co] = a;
}

__global__ void cm_kernel() {
    int b = blockIdx.y, n0 = blockIdx.x * 128, c = threadIdx.x;
    const __half* p = g_chmaph + (size_t)b * NN * Cc + c;
    float s = 0.f;
    for (int n = n0; n < n0 + 128; n++) s += __half2float(p[(size_t)n * Cc]);
    atomicAdd(&g_cm[b * Cc + c], s);
}

// ================================================================= launch ===
extern "C" void kernel_launch(void* const* d_in, const int* in_sizes, int n_in,
                              void* d_out, int out_size)
{
    const float* x           = (const float*)d_in[0];
    const float* temperature = (const float*)d_in[1];
    const float* qkv_w       = (const float*)d_in[2];
    const float* proj_w      = (const float*)d_in[3];
    const float* proj_b      = (const float*)d_in[4];
    const float* dw1_w       = (const float*)d_in[5];
    const float* dw1_b       = (const float*)d_in[6];
    const float* dw2_w       = (const float*)d_in[7];
    const float* dw2_b       = (const float*)d_in[8];
    const float* cp_in_w     = (const float*)d_in[9];
    const float* cp_in_b     = (const float*)d_in[10];
    const float* ci1_w       = (const float*)d_in[11];
    const float* ci1_b       = (const float*)d_in[12];
    const float* ci2a_w      = (const float*)d_in[13];
    const float* ci2a_b      = (const float*)d_in[14];
    const float* ci2b_w      = (const float*)d_in[15];
    const float* ci2b_b      = (const float*)d_in[16];
    const float* ci2c_w      = (const float*)d_in[17];
    const float* ci2c_b      = (const float*)d_in[18];
    const float* cp_out_w    = (const float*)d_in[19];
    const float* cp_out_b    = (const float*)d_in[20];
    const float* sp_in_w     = (const float*)d_in[21];
    const float* sp_in_b     = (const float*)d_in[22];
    const float* sp_dw_w     = (const float*)d_in[23];
    const float* sp_dw_b     = (const float*)d_in[24];
    const float* sp_out_w    = (const float*)d_in[25];
    const float* sp_out_b    = (const float*)d_in[26];
    float* out = (float*)d_out;

    __half *xh, *qkvh, *ath, *t1h, *convxh, *chmaph, *tth, *u1h, *u2h,
           *u3h, *sph, *gatedh, *yh, *wb;
    float *ssq, *ci1v, *cm;
    cudaGetSymbolAddress((void**)&xh,     g_xh);
    cudaGetSymbolAddress((void**)&qkvh,   g_qkvh);
    cudaGetSymbolAddress((void**)&ath,    g_ath);
    cudaGetSymbolAddress((void**)&t1h,    g_t1h);
    cudaGetSymbolAddress((void**)&convxh, g_convxh);
    cudaGetSymbolAddress((void**)&chmaph, g_chmaph);
    cudaGetSymbolAddress((void**)&tth,    g_tth);
    cudaGetSymbolAddress((void**)&u1h,    g_u1h);
    cudaGetSymbolAddress((void**)&u2h,    g_u2h);
    cudaGetSymbolAddress((void**)&u3h,    g_u3h);
    cudaGetSymbolAddress((void**)&sph,    g_sph);
    cudaGetSymbolAddress((void**)&gatedh, g_gatedh);
    cudaGetSymbolAddress((void**)&yh,     g_yh);
    cudaGetSymbolAddress((void**)&wb,     g_wbuf);
    cudaGetSymbolAddress((void**)&ssq,    g_sumsq);
    cudaGetSymbolAddress((void**)&ci1v,   g_ci1v);
    cudaGetSymbolAddress((void**)&cm,     g_cm);

    const long long bCN  = CN;
    const long long b3CN = (long long)NN * C3;
    const long long b64  = (long long)NN * C6c;
    const long long b192 = (long long)NN * C2c;
    const long long b128 = (long long)NN * 128;

    const int SM4 = (128 + 128) * RSH * 2 * 3;   // 110592 B
    const int SM3 = (128 + 96)  * RSH * 2 * 3;   // 96768 B
    const int SM2 = (128 + 64)  * RSH * 2 * 3;   // 82944 B

    // one-time handles (created on the uncaptured correctness call)
    static bool inited = false;
    static cudaStream_t sB, sC;
    static cudaEvent_t evStart, evPro, evQ, evB, evCP, evC;
    if (!inited) {
        cudaStreamCreateWithFlags(&sB, cudaStreamNonBlocking);
        cudaStreamCreateWithFlags(&sC, cudaStreamNonBlocking);
        cudaEventCreateWithFlags(&evStart, cudaEventDisableTiming);
        cudaEventCreateWithFlags(&evPro,   cudaEventDisableTiming);
        cudaEventCreateWithFlags(&evQ,     cudaEventDisableTiming);
        cudaEventCreateWithFlags(&evB,     cudaEventDisableTiming);
        cudaEventCreateWithFlags(&evCP,    cudaEventDisableTiming);
        cudaEventCreateWithFlags(&evC,     cudaEventDisableTiming);
        cudaFuncSetAttribute(mma_gemm<4>, cudaFuncAttributeMaxDynamicSharedMemorySize, SM4);
        cudaFuncSetAttribute(mma_gemm<3>, cudaFuncAttributeMaxDynamicSharedMemorySize, SM3);
        cudaFuncSetAttribute(mma_gemm<2>, cudaFuncAttributeMaxDynamicSharedMemorySize, SM2);
        inited = true;
    }

    WList wl;
    for (int k = 0; k < 8; k++) { wl.padK[k] = 0; wl.srcK[k] = 0; }
    wl.s[0]=qkv_w;   wl.n[0]=3*Cc*Cc;  wl.off[0]=W_QKV;
    wl.s[1]=dw1_w;   wl.n[1]=Cc*Cc;    wl.off[1]=W_DW1;
    wl.s[2]=cp_in_w; wl.n[2]=C6c*Cc;   wl.off[2]=W_CPIN;
    wl.s[3]=ci2c_w;  wl.n[3]=C6c*C6c;  wl.off[3]=W_CI2C;
    wl.s[4]=cp_out_w;wl.n[4]=Cc*C6c;   wl.off[4]=W_CPOUT;
    wl.s[5]=sp_in_w; wl.n[5]=C2c*Cc;   wl.off[5]=W_SPIN;
    wl.s[6]=sp_out_w;wl.n[6]=Cc*128;   wl.off[6]=W_SPOUT; wl.padK[6]=128; wl.srcK[6]=96;
    wl.s[7]=proj_w;  wl.n[7]=Cc*Cc;    wl.off[7]=W_PROJ;

    // -------- prologue: f2h on sB concurrent with zero+transpose on main ----
    cudaEventRecord(evStart, 0);
    cudaStreamWaitEvent(sB, evStart, 0);
    f2h_kernel<<<1728, 256, 0, sB>>>(wl);
    cudaEventRecord(evPro, sB);
    zero_kernel<<<576, 256>>>();
    transpose_kernel<<<dim3(128, 12, Bb), dim3(32, 8)>>>(x);
    cudaStreamWaitEvent(0, evPro, 0);

    // qkv (+ fused sumsq)
    mma_gemm<4><<<dim3(9, 32, Bb), 256, SM4>>>(xh, Cc, bCN, wb + W_QKV, Cc, 0,
        nullptr, 0, nullptr, nullptr, ssq, nullptr, nullptr, nullptr, nullptr,
        nullptr, qkvh, C3, b3CN, Cc);
    cudaEventRecord(evQ, 0);
    cudaStreamWaitEvent(sB, evQ, 0);

    // -------- branch B (conv/spatial) on sB ---------------------------------
    mma_gemm<4><<<dim3(3, 32, Bb), 256, SM4, sB>>>(qkvh + 2 * Cc, C3, b3CN,
        wb + W_DW1, Cc, 0, dw1_b, 0, nullptr, nullptr, nullptr,
        nullptr, nullptr, nullptr, nullptr, nullptr, t1h, Cc, bCN, Cc);
    dwconv4h<<<(Bb * NN * Cc / 4) / 256, 256, 0, sB>>>(t1h, dw2_w, dw2_b, convxh, Cc, 3, 1, 1);
    mma_gemm<3><<<dim3(2, 32, Bb), 256, SM3, sB>>>(convxh, Cc, bCN, wb + W_SPIN, Cc, 0,
        sp_in_b, 0, nullptr, nullptr, nullptr, nullptr, nullptr, nullptr, nullptr,
        nullptr, sph, C2c, b192, Cc);
    spdw_gelu<<<(Bb * NN * 24) / 256, 256, 0, sB>>>(sph, sp_dw_w, sp_dw_b, gatedh);
    cudaEventRecord(evB, sB);

    // -------- branch A (attention/channel) on main stream -------------------
    gram_kernel<<<dim3(4, Bb * HEADS), 256>>>();
    softmax_kernel<<<Bb * HEADS * HD, 64>>>(temperature);
    attnv_kernel<<<dim3(NN / 128, Bb * HEADS), 128>>>();
    mma_gemm<2><<<dim3(1, 32, Bb), 256, SM2>>>(ath, Cc, bCN, wb + W_CPIN, Cc, 0,
        cp_in_b, 0, nullptr, nullptr, nullptr, nullptr, nullptr, nullptr, nullptr,
        nullptr, tth, C6c, b64, Cc);
    cudaEventRecord(evCP, 0);
    // tmean + ci1 on sC, overlapped with ci2a/ci2b on main
    cudaStreamWaitEvent(sC, evCP, 0);
    tmean_kernel<<<dim3(32, Bb), 64, 0, sC>>>();
    ci1_kernel<<<Bb, C6c, 0, sC>>>(ci1_w, ci1_b);
    cudaEventRecord(evC, sC);
    dwconv4h<<<(Bb * NN * C6c / 4) / 256, 256>>>(tth, ci2a_w, ci2a_b, u1h, C6c, 3, 1, 1);
    dwconv4h<<<(Bb * NN * C6c / 4) / 256, 256>>>(u1h, ci2b_w, ci2b_b, u2h, C6c, 7, 9, 3);
    cudaStreamWaitEvent(0, evC, 0);
    mma_gemm<2><<<dim3(1, 32, Bb), 256, SM2>>>(u2h, C6c, b64, wb + W_CI2C, C6c, 0,
        ci2c_b, 0, tth, ci1v, nullptr, nullptr, nullptr, nullptr, nullptr,
        nullptr, u3h, C6c, b64, C6c);
    mma_gemm<4><<<dim3(3, 32, Bb), 256, SM4>>>(u3h, C6c, b64, wb + W_CPOUT, C6c, 0,
        cp_out_b, 0, nullptr, nullptr, nullptr, nullptr, nullptr, nullptr, nullptr,
        nullptr, chmaph, Cc, bCN, C6c);
    cm_kernel<<<dim3(32, Bb), Cc>>>();

    // -------- join, sp_out + fused combine, proj ----------------------------
    cudaStreamWaitEvent(0, evB, 0);
    mma_gemm<4><<<dim3(3, 32, Bb), 256, SM4>>>(gatedh, 128, b128, wb + W_SPOUT, 128, 0,
        sp_out_b, 0, nullptr, nullptr, nullptr, ath, chmaph, convxh, cm,
        nullptr, yh, Cc, bCN, 128);
    mma_gemm<4><<<dim3(32, 3, Bb), 256, SM4>>>(wb + W_PROJ, Cc, 0, yh, Cc, bCN,
        proj_b, 1, nullptr, nullptr, nullptr, nullptr, nullptr, nullptr, nullptr,
        out, nullptr, NN, bCN, Cc);
}

// round 15
// speedup vs baseline: 1.0705x; 1.0036x over previous
#include <cuda_runtime.h>
#include <cuda_fp16.h>
#include <cstdint>
#include <math.h>

#define Bb     8
#define Cc     384
#define NN     4096
#define HEADS  8
#define HD     48
#define CN     (Cc*NN)
#define C3     1152
#define C6c    64
#define C2c    192
#define C4c    96

// ---------------- scratch (all intermediates fp16; small stats fp32) ----------
__device__ __align__(16) __half g_xh    [Bb*NN*Cc];
__device__ __align__(16) __half g_qkvh  [(size_t)Bb*NN*C3];
__device__ __align__(16) __half g_ath   [Bb*NN*Cc];
__device__ __align__(16) __half g_t1h   [Bb*NN*Cc];
__device__ __align__(16) __half g_convxh[Bb*NN*Cc];
__device__ __align__(16) __half g_chmaph[Bb*NN*Cc];
__device__ __align__(16) __half g_tth   [Bb*NN*C6c];
__device__ __align__(16) __half g_u1h   [Bb*NN*C6c];
__device__ __align__(16) __half g_u2h   [Bb*NN*C6c];
__device__ __align__(16) __half g_u3h   [Bb*NN*C6c];
__device__ __align__(16) __half g_sph   [Bb*NN*C2c];
__device__ __align__(16) __half g_gatedh[Bb*NN*128];   // K padded 96 -> 128
__device__ __align__(16) __half g_yh    [Bb*NN*Cc];
__device__ __align__(16) __half g_wbuf  [917504];
__device__ float g_sumsq[Bb*2*Cc];
__device__ float g_gram [Bb*HEADS*HD*HD];
__device__ float g_attn [Bb*HEADS*HD*HD];
__device__ float g_tmean[Bb*C6c];
__device__ float g_ci1v [Bb*C6c];
__device__ float g_cm   [Bb*Cc];

#define W_QKV   0
#define W_DW1   442368
#define W_CPIN  589824
#define W_CI2C  614400
#define W_CPOUT 618496
#define W_SPIN  643072
#define W_SPOUT 716800      // padded: Cc rows x 128
#define W_PROJ  765952

__device__ __forceinline__ uint32_t smem_u32(const void* p) {
    uint32_t a;
    asm("{ .reg .u64 t; cvta.to.shared.u64 t, %1; cvt.u32.u64 %0, t; }" : "=r"(a) : "l"(p));
    return a;
}
__device__ __forceinline__ void cpa16u(uint32_t dst, const __half* src) {
    asm volatile("cp.async.cg.shared.global [%0], [%1], 16;"
                 :: "r"(dst), "l"(__cvta_generic_to_global(src)) : "memory");
}
#define CP_COMMIT() asm volatile("cp.async.commit_group;" ::: "memory")
#define CP_WAIT1()  asm volatile("cp.async.wait_group 1;" ::: "memory")
#define CP_WAIT0()  asm volatile("cp.async.wait_group 0;" ::: "memory")

__device__ __forceinline__ void ldsm4(uint32_t* r, uint32_t addr) {
    asm volatile("ldmatrix.sync.aligned.m8n8.x4.shared.b16 {%0,%1,%2,%3}, [%4];"
        : "=r"(r[0]), "=r"(r[1]), "=r"(r[2]), "=r"(r[3]) : "r"(addr));
}
__device__ __forceinline__ void ldsm4t(uint32_t* r, uint32_t addr) {
    asm volatile("ldmatrix.sync.aligned.m8n8.x4.trans.shared.b16 {%0,%1,%2,%3}, [%4];"
        : "=r"(r[0]), "=r"(r[1]), "=r"(r[2]), "=r"(r[3]) : "r"(addr));
}
__device__ __forceinline__ void ldsm2(uint32_t* r, uint32_t addr) {
    asm volatile("ldmatrix.sync.aligned.m8n8.x2.shared.b16 {%0,%1}, [%2];"
        : "=r"(r[0]), "=r"(r[1]) : "r"(addr));
}
__device__ __forceinline__ void mma_f16(float* d, uint32_t a0, uint32_t a1,
                                        uint32_t a2, uint32_t a3,
                                        uint32_t b0, uint32_t b1) {
    asm volatile(
        "mma.sync.aligned.m16n8k16.row.col.f32.f16.f16.f32 "
        "{%0,%1,%2,%3}, {%4,%5,%6,%7}, {%8,%9}, {%0,%1,%2,%3};"
        : "+f"(d[0]), "+f"(d[1]), "+f"(d[2]), "+f"(d[3])
        : "r"(a0), "r"(a1), "r"(a2), "r"(a3), "r"(b0), "r"(b1));
}
__device__ __forceinline__ float sigf(float v) { return 1.f / (1.f + expf(-v)); }

// ---------------- 3-stage pipelined fp16 ldmatrix GEMM, BK=64 -------------------
#define RSH 72       // halves per smem row (144B): conflict-free ldmatrix
template<int NI>
__global__ __launch_bounds__(256, 2)
void mma_gemm(const __half* __restrict__ A, int lda, long long abatch,
              const __half* __restrict__ B, int ldb, long long bbatch,
              const float* __restrict__ bias, int biasRowMode,
              const __half* __restrict__ emul, const float* __restrict__ escale,
              float* __restrict__ ssq,
              float* __restrict__ csum, int csumStride,
              const __half* __restrict__ cAt, const __half* __restrict__ cCh,
              const __half* __restrict__ cCv, const float* __restrict__ cCm,
              float* __restrict__ Outf, __half* __restrict__ Outh,
              int ldo, long long obatch, int K)
{
    constexpr int n_tile = NI * 32;
    constexpr uint32_t STAGEB = (128 + n_tile) * RSH * 2;
    extern __shared__ __half sh[];
    const uint32_t smBase = smem_u32(sh);

    const int tid  = threadIdx.x;
    const int wid  = tid >> 5, lane = tid & 31;
    const int g    = lane >> 2, tig = lane & 3;
    const int z    = blockIdx.z;
    const int arow0 = blockIdx.y * 128;
    const int brow0 = blockIdx.x * n_tile;
    const int wm = (wid & 1) * 64;
    const int wn = (wid >> 1) * (NI * 8);

    const __half* Ab = A + (size_t)z * abatch + (size_t)arow0 * lda;
    const __half* Bp = B + (size_t)z * bbatch + (size_t)brow0 * ldb;

    const __half* aSrc[4];  uint32_t aDst[4];
    #pragma unroll
    for (int i = 0; i < 4; i++) {
        int e = tid + i * 256;
        aSrc[i] = Ab + (size_t)(e >> 3) * lda + (e & 7) * 8;
        aDst[i] = ((e >> 3) * RSH + (e & 7) * 8) * 2;
    }
    const __half* bSrc[NI]; uint32_t bDst[NI];
    #pragma unroll
    for (int i = 0; i < NI; i++) {
        int e = tid + i * 256;
        bSrc[i] = Bp + (size_t)(e >> 3) * ldb + (e & 7) * 8;
        bDst[i] = (128 * RSH + (e >> 3) * RSH + (e & 7) * 8) * 2;
    }

    uint32_t aOff[4];
    #pragma unroll
    for (int mi = 0; mi < 4; mi++)
        aOff[mi] = (((wm + mi * 16 + (lane & 15)) * RSH) + (lane >> 4) * 8) * 2;
    uint32_t bPairOff[(NI + 1) / 2];
    #pragma unroll
    for (int np = 0; np < NI / 2; np++)
        bPairOff[np] = ((128 + wn + np * 16 + ((lane >> 4) << 3) + (lane & 7)) * RSH +
                        ((lane >> 3) & 1) * 8) * 2;
    uint32_t bSoloOff = ((128 + wn + (NI - 1) * 8 + (lane & 7)) * RSH +
                         ((lane >> 3) & 1) * 8) * 2;

    float c[4][NI][4];
    #pragma unroll
    for (int mi = 0; mi < 4; mi++)
        #pragma unroll
        for (int ni = 0; ni < NI; ni++)
            #pragma unroll
            for (int q = 0; q < 4; q++) c[mi][ni][q] = 0.f;

    auto loadTiles = [&](int kc, uint32_t stBase) {
        const int koff = kc * 64;
        #pragma unroll
        for (int i = 0; i < 4; i++)
            cpa16u(stBase + aDst[i], aSrc[i] + koff);
        #pragma unroll
        for (int i = 0; i < NI; i++)
            cpa16u(stBase + bDst[i], bSrc[i] + koff);
        CP_COMMIT();
    };

    const int nch = K >> 6;
    loadTiles(0, smBase);
    if (nch > 1) loadTiles(1, smBase + STAGEB); else CP_COMMIT();

    uint32_t smC = smBase;
    uint32_t smL = smBase + 2 * STAGEB;
    for (int kc = 0; kc < nch; kc++) {
        CP_WAIT1();
        __syncthreads();
        if (kc + 2 < nch) loadTiles(kc + 2, smL); else CP_COMMIT();

        #pragma unroll
        for (int ks = 0; ks < 4; ks++) {
            const uint32_t kb = ks * 32;
            uint32_t a[4][4];
            #pragma unroll
            for (int mi = 0; mi < 4; mi++)
                ldsm4(a[mi], smC + aOff[mi] + kb);
            uint32_t b[NI][2];
            #pragma unroll
            for (int np = 0; np < NI / 2; np++) {
                uint32_t r[4]; ldsm4(r, smC + bPairOff[np] + kb);
                b[2*np][0] = r[0]; b[2*np][1] = r[1];
                b[2*np+1][0] = r[2]; b[2*np+1][1] = r[3];
            }
            if (NI & 1) ldsm2(b[NI-1], smC + bSoloOff + kb);
            #pragma unroll
            for (int ni = 0; ni < NI; ni++)
                #pragma unroll
                for (int mi = 0; mi < 4; mi++)
                    mma_f16(c[mi][ni], a[mi][0], a[mi][1], a[mi][2], a[mi][3],
                            b[ni][0], b[ni][1]);
        }
        smC = (smC == smBase + 2 * STAGEB) ? smBase : smC + STAGEB;
        smL = (smL == smBase + 2 * STAGEB) ? smBase : smL + STAGEB;
    }

    if (ssq) {
        #pragma unroll
        for (int ni = 0; ni < NI; ni++) {
            int col = brow0 + wn + ni * 8 + tig * 2;
            if (col < 2 * Cc) {
                float s0 = 0.f, s1 = 0.f;
                #pragma unroll
                for (int mi = 0; mi < 4; mi++) {
                    s0 += c[mi][ni][0] * c[mi][ni][0] + c[mi][ni][2] * c[mi][ni][2];
                    s1 += c[mi][ni][1] * c[mi][ni][1] + c[mi][ni][3] * c[mi][ni][3];
                }
                s0 += __shfl_xor_sync(0xffffffffu, s0, 4);
                s1 += __shfl_xor_sync(0xffffffffu, s1, 4);
                s0 += __shfl_xor_sync(0xffffffffu, s0, 8);
                s1 += __shfl_xor_sync(0xffffffffu, s1, 8);
                s0 += __shfl_xor_sync(0xffffffffu, s0, 16);
                s1 += __shfl_xor_sync(0xffffffffu, s1, 16);
                if (g == 0) {
                    atomicAdd(&ssq[z * 2 * Cc + col], s0);
                    atomicAdd(&ssq[z * 2 * Cc + col + 1], s1);
                }
            }
        }
    }

    float colsum0[NI], colsum1[NI];
    #pragma unroll
    for (int ni = 0; ni < NI; ni++) { colsum0[ni] = 0.f; colsum1[ni] = 0.f; }

    #pragma unroll
    for (int mi = 0; mi < 4; mi++) {
        const int row = arow0 + wm + mi * 16 + g;
        float bv0 = 0.f, bv1 = 0.f;
        if (bias && biasRowMode) { bv0 = bias[row]; bv1 = bias[row + 8]; }
        #pragma unroll
        for (int ni = 0; ni < NI; ni++) {
            const int col = brow0 + wn + ni * 8 + tig * 2;
            float bc0 = 0.f, bc1 = 0.f;
            if (bias && !biasRowMode) { bc0 = bias[col]; bc1 = bias[col + 1]; }
            size_t o0 = (size_t)z * obatch + (size_t)row * ldo + col;
            size_t o1 = o0 + 8 * (size_t)ldo;
            float v00 = c[mi][ni][0] + bv0 + bc0, v01 = c[mi][ni][1] + bv0 + bc1;
            float v10 = c[mi][ni][2] + bv1 + bc0, v11 = c[mi][ni][3] + bv1 + bc1;
            if (emul) {
                float2 m0 = __half22float2(*(const __half2*)(emul + o0));
                float2 m1 = __half22float2(*(const __half2*)(emul + o1));
                float s0 = escale[z * C6c + col], s1 = escale[z * C6c + col + 1];
                v00 *= m0.x * s0; v01 *= m0.y * s1;
                v10 *= m1.x * s0; v11 *= m1.y * s1;
            }
            if (cAt) {
                float sc0 = sigf(cCm[z * Cc + col] * (1.f / NN));
                float sc1 = sigf(cCm[z * Cc + col + 1] * (1.f / NN));
                float2 a0 = __half22float2(*(const __half2*)(cAt + o0));
                float2 a1 = __half22float2(*(const __half2*)(cAt + o1));
                float2 h0 = __half22float2(*(const __half2*)(cCh + o0));
                float2 h1 = __half22float2(*(const __half2*)(cCh + o1));
                float2 w0 = __half22float2(*(const __half2*)(cCv + o0));
                float2 w1 = __half22float2(*(const __half2*)(cCv + o1));
                v00 = (a0.x + h0.x) * sigf(v00) + w0.x * sc0;
                v01 = (a0.y + h0.y) * sigf(v01) + w0.y * sc1;
                v10 = (a1.x + h1.x) * sigf(v10) + w1.x * sc0;
                v11 = (a1.y + h1.y) * sigf(v11) + w1.y * sc1;
            }
            if (csum) {
                colsum0[ni] += v00 + v10;
                colsum1[ni] += v01 + v11;
            }
            if (Outh) {
                *(__half2*)(Outh + o0) = __floats2half2_rn(v00, v01);
                *(__half2*)(Outh + o1) = __floats2half2_rn(v10, v11);
            } else {
                *(float2*)(Outf + o0) = make_float2(v00, v01);
                *(float2*)(Outf + o1) = make_float2(v10, v11);
            }
        }
    }

    // fused column sum (for tmean / cm): sum over this CTA's 128 rows
    if (csum) {
        #pragma unroll
        for (int ni = 0; ni < NI; ni++) {
            const int col = brow0 + wn + ni * 8 + tig * 2;
            float s0 = colsum0[ni], s1 = colsum1[ni];
            s0 += __shfl_xor_sync(0xffffffffu, s0, 4);
            s1 += __shfl_xor_sync(0xffffffffu, s1, 4);
            s0 += __shfl_xor_sync(0xffffffffu, s0, 8);
            s1 += __shfl_xor_sync(0xffffffffu, s1, 8);
            s0 += __shfl_xor_sync(0xffffffffu, s0, 16);
            s1 += __shfl_xor_sync(0xffffffffu, s1, 16);
            if (g == 0) {
                atomicAdd(&csum[z * csumStride + col], s0);
                atomicAdd(&csum[z * csumStride + col + 1], s1);
            }
        }
    }
}

// ---------------- weight fp32 -> fp16 (entry may be K-padded) -------------------
struct WList { const float* s[8]; int n[8]; int off[8]; int padK[8]; int srcK[8]; };
__global__ void f2h_kernel(WList wl) {
    int idx = blockIdx.x * 256 + threadIdx.x;
    #pragma unroll
    for (int k = 0; k < 8; k++) {
        if (idx < wl.n[k]) {
            float v;
            if (wl.padK[k]) {
                int r = idx / wl.padK[k], kk = idx % wl.padK[k];
                v = (kk < wl.srcK[k]) ? wl.s[k][r * wl.srcK[k] + kk] : 0.f;
            } else v = wl.s[k][idx];
            g_wbuf[wl.off[k] + idx] = __float2half(v);
        }
    }
}

__global__ void zero_kernel() {
    int i = blockIdx.x * 256 + threadIdx.x;
    if (i < Bb*2*Cc)          g_sumsq[i] = 0.f;
    if (i < Bb*HEADS*HD*HD)   g_gram[i]  = 0.f;
    if (i < Bb*C6c)           g_tmean[i] = 0.f;
    if (i < Bb*Cc)            g_cm[i]    = 0.f;
    if (i < Bb*NN*4) {
        int row = i >> 2, seg = i & 3;
        *(uint4*)(g_gatedh + (size_t)row * 128 + 96 + seg * 8) = make_uint4(0,0,0,0);
    }
}

__global__ void transpose_kernel(const float* __restrict__ in) {
    __shared__ float t[32][33];
    int b = blockIdx.z, c0 = blockIdx.y * 32, n0 = blockIdx.x * 32;
    int tx = threadIdx.x, ty = threadIdx.y;
    for (int i = ty; i < 32; i += 8)
        t[i][tx] = in[(size_t)b * CN + (size_t)(c0 + i) * NN + n0 + tx];
    __syncthreads();
    for (int i = ty; i < 32; i += 8)
        g_xh[(size_t)b * CN + (size_t)(n0 + i) * Cc + c0 + tx] = __float2half(t[tx][i]);
}

// ---------------- MMA gram ------------------------------------------------------
__global__ __launch_bounds__(256) void gram_kernel() {
    int bh = blockIdx.y; int b = bh >> 3, h = bh & 7;
    int nbase = blockIdx.x * 1024;
    const __half* qp = g_qkvh + (size_t)b * NN * C3 + h * HD;
    const __half* kp = qp + Cc;
    __shared__ __align__(16) __half qs[128 * 56];
    __shared__ __align__(16) __half ks_[128 * 56];
    __shared__ float gsm[HD * HD];
    int tid = threadIdx.x, wid = tid >> 5, lane = tid & 31;
    int g = lane >> 2, t = lane & 3;
    for (int i = tid; i < HD * HD; i += 256) gsm[i] = 0.f;

    float c[3][6][4];
    #pragma unroll
    for (int mi = 0; mi < 3; mi++)
        #pragma unroll
        for (int nt = 0; nt < 6; nt++)
            #pragma unroll
            for (int q = 0; q < 4; q++) c[mi][nt][q] = 0.f;

    for (int ch = 0; ch < 8; ch++) {
        __syncthreads();
        for (int e = tid; e < 768; e += 256) {
            int r = e / 6, s = e % 6;
            size_t goff = (size_t)(nbase + ch * 128 + r) * C3 + s * 8;
            cpa16u(smem_u32(qs  + r * 56 + s * 8), qp + goff);
            cpa16u(smem_u32(ks_ + r * 56 + s * 8), kp + goff);
        }
        CP_COMMIT(); CP_WAIT0();
        __syncthreads();

        int nrow = wid * 16;
        uint32_t a[3][4], bb[6][2];
        #pragma unroll
        for (int mi = 0; mi < 3; mi++) {
            int row = nrow + (lane & 7) + ((lane >> 4) << 3);
            int col = mi * 16 + ((lane >> 3) & 1) * 8;
            ldsm4t(a[mi], smem_u32(qs) + (row * 56 + col) * 2);
        }
        #pragma unroll
        for (int p = 0; p < 3; p++) {
            int row = nrow + (lane & 7) + ((lane >> 3) & 1) * 8;
            int col = p * 16 + (lane >> 4) * 8;
            uint32_t r[4];
            ldsm4t(r, smem_u32(ks_) + (row * 56 + col) * 2);
            bb[2*p][0] = r[0]; bb[2*p][1] = r[1];
            bb[2*p+1][0] = r[2]; bb[2*p+1][1] = r[3];
        }
        #pragma unroll
        for (int mi = 0; mi < 3; mi++)
            #pragma unroll
            for (int nt = 0; nt < 6; nt++)
                mma_f16(c[mi][nt], a[mi][0], a[mi][1], a[mi][2], a[mi][3],
                        bb[nt][0], bb[nt][1]);
    }

    #pragma unroll
    for (int mi = 0; mi < 3; mi++)
        #pragma unroll
        for (int nt = 0; nt < 6; nt++)
            #pragma unroll
            for (int q = 0; q < 4; q++) {
                int i = mi * 16 + g + ((q & 2) ? 8 : 0);
                int j = nt * 8 + 2 * t + (q & 1);
                atomicAdd(&gsm[i * HD + j], c[mi][nt][q]);
            }
    __syncthreads();
    for (int i = tid; i < HD * HD; i += 256)
        atomicAdd(&g_gram[(size_t)bh * HD * HD + i], gsm[i]);
}

__global__ void softmax_kernel(const float* __restrict__ temp) {
    int gi = blockIdx.x;
    int i = gi % HD; int bh = gi / HD;
    int b = bh >> 3, h = bh & 7;
    int tid = threadIdx.x;
    float qi = rsqrtf(fmaxf(g_sumsq[b * 2 * Cc + h * HD + i], 1e-24f));
    float v = -3.4e38f;
    if (tid < HD) {
        float kj = rsqrtf(fmaxf(g_sumsq[b * 2 * Cc + Cc + h * HD + tid], 1e-24f));
        v = g_gram[(size_t)bh * HD * HD + i * HD + tid] * qi * kj * temp[h];
    }
    __shared__ float red[64];
    red[tid] = v; __syncthreads();
    for (int st = 32; st > 0; st >>= 1) {
        if (tid < st) red[tid] = fmaxf(red[tid], red[tid + st]);
        __syncthreads();
    }
    float m = red[0]; __syncthreads();
    float e = (tid < HD) ? expf(v - m) : 0.f;
    red[tid] = e; __syncthreads();
    for (int st = 32; st > 0; st >>= 1) {
        if (tid < st) red[tid] += red[tid + st];
        __syncthreads();
    }
    if (tid < HD) g_attn[(size_t)bh * HD * HD + i * HD + tid] = e / red[0];
}

__global__ __launch_bounds__(128) void attnv_kernel() {
    int bh = blockIdx.y; int b = bh >> 3, h = bh & 7;
    int n = blockIdx.x * 128 + threadIdx.x;
    __shared__ float sa[HD * HD];
    for (int e = threadIdx.x; e < HD * HD; e += 128)
        sa[e] = g_attn[(size_t)bh * HD * HD + e];
    __syncthreads();
    const __half* vp = g_qkvh + (size_t)(b * NN + n) * C3 + 2 * Cc + h * HD;
    float vr[HD];
    #pragma unroll
    for (int j6 = 0; j6 < 6; j6++) {
        uint4 u = ((const uint4*)vp)[j6];
        const __half2* hp = (const __half2*)&u;
        #pragma unroll
        for (int q = 0; q < 4; q++) {
            float2 f = __half22float2(hp[q]);
            vr[j6 * 8 + q * 2] = f.x; vr[j6 * 8 + q * 2 + 1] = f.y;
        }
    }
    __half* oph = g_ath + (size_t)(b * NN + n) * Cc + h * HD;
    #pragma unroll
    for (int i0 = 0; i0 < HD; i0 += 8) {
        float res[8];
        #pragma unroll
        for (int i = 0; i < 8; i++) {
            float s = 0.f;
            #pragma unroll
            for (int j = 0; j < HD; j++) s += sa[(i0 + i) * HD + j] * vr[j];
            res[i] = s;
        }
        __half2 hres[4];
        #pragma unroll
        for (int q = 0; q < 4; q++)
            hres[q] = __floats2half2_rn(res[q*2], res[q*2+1]);
        *(uint4*)(oph + i0) = *(uint4*)hres;
    }
}

// fp16-in fp16-out depthwise conv (NHWC, C % 4 == 0), fp32 accumulate
__global__ void dwconv4h(const __half* __restrict__ in, const float* __restrict__ w,
                         const float* __restrict__ bias, __half* __restrict__ out,
                         int C, int ks, int pad, int dil)
{
    int idx = blockIdx.x * 256 + threadIdx.x;
    int C4 = C >> 2;
    int c4 = idx % C4; int rest = idx / C4;
    int xx = rest & 63, yy = (rest >> 6) & 63, b = rest >> 12;
    int c = c4 << 2;
    const __half* ip = in + (size_t)(b * NN) * C + c;
    float4 bv = *(const float4*)(bias + c);
    float a0 = bv.x, a1 = bv.y, a2 = bv.z, a3 = bv.w;
    const float* wp = w + c * ks * ks;
    const int K2 = ks * ks;
    for (int ky = 0; ky < ks; ky++) {
        int y = yy - pad + ky * dil;
        if ((unsigned)y >= 64u) continue;
        for (int kx = 0; kx < ks; kx++) {
            int x = xx - pad + kx * dil;
            if ((unsigned)x >= 64u) continue;
            uint2 u = *(const uint2*)(ip + (size_t)(y * 64 + x) * C);
            const __half2* hp = (const __half2*)&u;
            float2 f0 = __half22float2(hp[0]), f1 = __half22float2(hp[1]);
            int t = ky * ks + kx;
            a0 += f0.x * wp[t];
            a1 += f0.y * wp[t + K2];
            a2 += f1.x * wp[t + 2 * K2];
            a3 += f1.y * wp[t + 3 * K2];
        }
    }
    __half2 hh[2] = {__floats2half2_rn(a0, a1), __floats2half2_rn(a2, a3)};
    *(uint2*)(out + (size_t)(b * NN + yy * 64 + xx) * C + c) = *(uint2*)hh;
}

// fused sp_dw (3x3 depthwise over C2c, fp16 in) + gelu gate -> gated (stride 128)
__global__ void spdw_gelu(const __half* __restrict__ sp, const float* __restrict__ w,
                          const float* __restrict__ bias, __half* __restrict__ out)
{
    int idx = blockIdx.x * 256 + threadIdx.x;
    int c4 = idx % 24; int rest = idx / 24;
    int xx = rest & 63, yy = (rest >> 6) & 63, b = rest >> 12;
    int c = c4 << 2;
    const __half* ip = sp + (size_t)(b * NN) * C2c;
    float4 bv1 = *(const float4*)(bias + c);
    float4 bv2 = *(const float4*)(bias + c + C4c);
    float a1[4] = {bv1.x, bv1.y, bv1.z, bv1.w};
    float a2[4] = {bv2.x, bv2.y, bv2.z, bv2.w};
    const float* w1 = w + c * 9;
    const float* w2 = w + (c + C4c) * 9;
    #pragma unroll
    for (int ky = 0; ky < 3; ky++) {
        int y = yy - 1 + ky;
        if ((unsigned)y >= 64u) continue;
        #pragma unroll
        for (int kx = 0; kx < 3; kx++) {
            int x = xx - 1 + kx;
            if ((unsigned)x >= 64u) continue;
            const __half* pv = ip + (size_t)(y * 64 + x) * C2c + c;
            uint2 u1v = *(const uint2*)pv;
            uint2 u2v = *(const uint2*)(pv + C4c);
            const __half2* h1 = (const __half2*)&u1v;
            const __half2* h2 = (const __half2*)&u2v;
            float2 f10 = __half22float2(h1[0]), f11 = __half22float2(h1[1]);
            float2 f20 = __half22float2(h2[0]), f21 = __half22float2(h2[1]);
            int t = ky * 3 + kx;
            a1[0] += f10.x * w1[t];      a1[1] += f10.y * w1[t + 9];
            a1[2] += f11.x * w1[t + 18]; a1[3] += f11.y * w1[t + 27];
            a2[0] += f20.x * w2[t];      a2[1] += f20.y * w2[t + 9];
            a2[2] += f21.x * w2[t + 18]; a2[3] += f21.y * w2[t + 27];
        }
    }
    float o[4];
    #pragma unroll
    for (int q = 0; q < 4; q++) {
        float gg = 0.5f * a1[q] * (1.f + erff(a1[q] * 0.70710678118654752f));
        o[q] = gg * a2[q];
    }
    __half2 hh[2] = {__floats2half2_rn(o[0], o[1]), __floats2half2_rn(o[2], o[3])};
    *(uint2*)(out + (size_t)(b * NN + yy * 64 + xx) * 128 + c) = *(uint2*)hh;
}

__global__ void ci1_kernel(const float* __restrict__ w, const float* __restrict__ bias) {
    int b = blockIdx.x, co = threadIdx.x;
    __shared__ float tm[C6c];
    tm[co] = g_tmean[b * C6c + co] * (1.f / NN);
    __syncthreads();
    float a = bias[co];
    #pragma unroll
    for (int ci = 0; ci < C6c; ci++) a += w[co * C6c + ci] * tm[ci];
    g_ci1v[b * C6c + co] = a;
}

// ================================================================= launch ===
extern "C" void kernel_launch(void* const* d_in, const int* in_sizes, int n_in,
                              void* d_out, int out_size)
{
    const float* x           = (const float*)d_in[0];
    const float* temperature = (const float*)d_in[1];
    const float* qkv_w       = (const float*)d_in[2];
    const float* proj_w      = (const float*)d_in[3];
    const float* proj_b      = (const float*)d_in[4];
    const float* dw1_w       = (const float*)d_in[5];
    const float* dw1_b       = (const float*)d_in[6];
    const float* dw2_w       = (const float*)d_in[7];
    const float* dw2_b       = (const float*)d_in[8];
    const float* cp_in_w     = (const float*)d_in[9];
    const float* cp_in_b     = (const float*)d_in[10];
    const float* ci1_w       = (const float*)d_in[11];
    const float* ci1_b       = (const float*)d_in[12];
    const float* ci2a_w      = (const float*)d_in[13];
    const float* ci2a_b      = (const float*)d_in[14];
    const float* ci2b_w      = (const float*)d_in[15];
    const float* ci2b_b      = (const float*)d_in[16];
    const float* ci2c_w      = (const float*)d_in[17];
    const float* ci2c_b      = (const float*)d_in[18];
    const float* cp_out_w    = (const float*)d_in[19];
    const float* cp_out_b    = (const float*)d_in[20];
    const float* sp_in_w     = (const float*)d_in[21];
    const float* sp_in_b     = (const float*)d_in[22];
    const float* sp_dw_w     = (const float*)d_in[23];
    const float* sp_dw_b     = (const float*)d_in[24];
    const float* sp_out_w    = (const float*)d_in[25];
    const float* sp_out_b    = (const float*)d_in[26];
    float* out = (float*)d_out;

    __half *xh, *qkvh, *ath, *t1h, *convxh, *chmaph, *tth, *u1h, *u2h,
           *u3h, *sph, *gatedh, *yh, *wb;
    float *ssq, *ci1v, *cm, *tmean;
    cudaGetSymbolAddress((void**)&xh,     g_xh);
    cudaGetSymbolAddress((void**)&qkvh,   g_qkvh);
    cudaGetSymbolAddress((void**)&ath,    g_ath);
    cudaGetSymbolAddress((void**)&t1h,    g_t1h);
    cudaGetSymbolAddress((void**)&convxh, g_convxh);
    cudaGetSymbolAddress((void**)&chmaph, g_chmaph);
    cudaGetSymbolAddress((void**)&tth,    g_tth);
    cudaGetSymbolAddress((void**)&u1h,    g_u1h);
    cudaGetSymbolAddress((void**)&u2h,    g_u2h);
    cudaGetSymbolAddress((void**)&u3h,    g_u3h);
    cudaGetSymbolAddress((void**)&sph,    g_sph);
    cudaGetSymbolAddress((void**)&gatedh, g_gatedh);
    cudaGetSymbolAddress((void**)&yh,     g_yh);
    cudaGetSymbolAddress((void**)&wb,     g_wbuf);
    cudaGetSymbolAddress((void**)&ssq,    g_sumsq);
    cudaGetSymbolAddress((void**)&ci1v,   g_ci1v);
    cudaGetSymbolAddress((void**)&cm,     g_cm);
    cudaGetSymbolAddress((void**)&tmean,  g_tmean);

    const long long bCN  = CN;
    const long long b3CN = (long long)NN * C3;
    const long long b64  = (long long)NN * C6c;
    const long long b192 = (long long)NN * C2c;
    const long long b128 = (long long)NN * 128;

    const int SM4 = (128 + 128) * RSH * 2 * 3;   // 110592 B
    const int SM3 = (128 + 96)  * RSH * 2 * 3;   // 96768 B
    const int SM2 = (128 + 64)  * RSH * 2 * 3;   // 82944 B

    static bool inited = false;
    static cudaStream_t sB, sC;
    static cudaEvent_t evStart, evPro, evQ, evB, evCP, evC;
    if (!inited) {
        cudaStreamCreateWithFlags(&sB, cudaStreamNonBlocking);
        cudaStreamCreateWithFlags(&sC, cudaStreamNonBlocking);
        cudaEventCreateWithFlags(&evStart, cudaEventDisableTiming);
        cudaEventCreateWithFlags(&evPro,   cudaEventDisableTiming);
        cudaEventCreateWithFlags(&evQ,     cudaEventDisableTiming);
        cudaEventCreateWithFlags(&evB,     cudaEventDisableTiming);
        cudaEventCreateWithFlags(&evCP,    cudaEventDisableTiming);
        cudaEventCreateWithFlags(&evC,     cudaEventDisableTiming);
        cudaFuncSetAttribute(mma_gemm<4>, cudaFuncAttributeMaxDynamicSharedMemorySize, SM4);
        cudaFuncSetAttribute(mma_gemm<3>, cudaFuncAttributeMaxDynamicSharedMemorySize, SM3);
        cudaFuncSetAttribute(mma_gemm<2>, cudaFuncAttributeMaxDynamicSharedMemorySize, SM2);
        inited = true;
    }

    WList wl;
    for (int k = 0; k < 8; k++) { wl.padK[k] = 0; wl.srcK[k] = 0; }
    wl.s[0]=qkv_w;   wl.n[0]=3*Cc*Cc;  wl.off[0]=W_QKV;
    wl.s[1]=dw1_w;   wl.n[1]=Cc*Cc;    wl.off[1]=W_DW1;
    wl.s[2]=cp_in_w; wl.n[2]=C6c*Cc;   wl.off[2]=W_CPIN;
    wl.s[3]=ci2c_w;  wl.n[3]=C6c*C6c;  wl.off[3]=W_CI2C;
    wl.s[4]=cp_out_w;wl.n[4]=Cc*C6c;   wl.off[4]=W_CPOUT;
    wl.s[5]=sp_in_w; wl.n[5]=C2c*Cc;   wl.off[5]=W_SPIN;
    wl.s[6]=sp_out_w;wl.n[6]=Cc*128;   wl.off[6]=W_SPOUT; wl.padK[6]=128; wl.srcK[6]=96;
    wl.s[7]=proj_w;  wl.n[7]=Cc*Cc;    wl.off[7]=W_PROJ;

    // -------- prologue: f2h on sB concurrent with zero+transpose on main ----
    cudaEventRecord(evStart, 0);
    cudaStreamWaitEvent(sB, evStart, 0);
    f2h_kernel<<<1728, 256, 0, sB>>>(wl);
    cudaEventRecord(evPro, sB);
    zero_kernel<<<576, 256>>>();
    transpose_kernel<<<dim3(128, 12, Bb), dim3(32, 8)>>>(x);
    cudaStreamWaitEvent(0, evPro, 0);

    // qkv (+ fused sumsq)
    mma_gemm<4><<<dim3(9, 32, Bb), 256, SM4>>>(xh, Cc, bCN, wb + W_QKV, Cc, 0,
        nullptr, 0, nullptr, nullptr, ssq, nullptr, 0,
        nullptr, nullptr, nullptr, nullptr, nullptr, qkvh, C3, b3CN, Cc);
    cudaEventRecord(evQ, 0);
    cudaStreamWaitEvent(sB, evQ, 0);

    // -------- branch B (conv/spatial) on sB ---------------------------------
    mma_gemm<4><<<dim3(3, 32, Bb), 256, SM4, sB>>>(qkvh + 2 * Cc, C3, b3CN,
        wb + W_DW1, Cc, 0, dw1_b, 0, nullptr, nullptr, nullptr, nullptr, 0,
        nullptr, nullptr, nullptr, nullptr, nullptr, t1h, Cc, bCN, Cc);
    dwconv4h<<<(Bb * NN * Cc / 4) / 256, 256, 0, sB>>>(t1h, dw2_w, dw2_b, convxh, Cc, 3, 1, 1);
    mma_gemm<3><<<dim3(2, 32, Bb), 256, SM3, sB>>>(convxh, Cc, bCN, wb + W_SPIN, Cc, 0,
        sp_in_b, 0, nullptr, nullptr, nullptr, nullptr, 0,
        nullptr, nullptr, nullptr, nullptr, nullptr, sph, C2c, b192, Cc);
    spdw_gelu<<<(Bb * NN * 24) / 256, 256, 0, sB>>>(sph, sp_dw_w, sp_dw_b, gatedh);
    cudaEventRecord(evB, sB);

    // -------- branch A (attention/channel) on main stream -------------------
    gram_kernel<<<dim3(4, Bb * HEADS), 256>>>();
    softmax_kernel<<<Bb * HEADS * HD, 64>>>(temperature);
    attnv_kernel<<<dim3(NN / 128, Bb * HEADS), 128>>>();
    // cp_in with fused tmean column-sum
    mma_gemm<2><<<dim3(1, 32, Bb), 256, SM2>>>(ath, Cc, bCN, wb + W_CPIN, Cc, 0,
        cp_in_b, 0, nullptr, nullptr, nullptr, tmean, C6c,
        nullptr, nullptr, nullptr, nullptr, nullptr, tth, C6c, b64, Cc);
    cudaEventRecord(evCP, 0);
    // ci1 on sC, overlapped with ci2a/ci2b on main
    cudaStreamWaitEvent(sC, evCP, 0);
    ci1_kernel<<<Bb, C6c, 0, sC>>>(ci1_w, ci1_b);
    cudaEventRecord(evC, sC);
    dwconv4h<<<(Bb * NN * C6c / 4) / 256, 256>>>(tth, ci2a_w, ci2a_b, u1h, C6c, 3, 1, 1);
    dwconv4h<<<(Bb * NN * C6c / 4) / 256, 256>>>(u1h, ci2b_w, ci2b_b, u2h, C6c, 7, 9, 3);
    cudaStreamWaitEvent(0, evC, 0);
    mma_gemm<2><<<dim3(1, 32, Bb), 256, SM2>>>(u2h, C6c, b64, wb + W_CI2C, C6c, 0,
        ci2c_b, 0, tth, ci1v, nullptr, nullptr, 0,
        nullptr, nullptr, nullptr, nullptr, nullptr, u3h, C6c, b64, C6c);
    // cp_out with fused cm column-sum
    mma_gemm<4><<<dim3(3, 32, Bb), 256, SM4>>>(u3h, C6c, b64, wb + W_CPOUT, C6c, 0,
        cp_out_b, 0, nullptr, nullptr, nullptr, cm, Cc,
        nullptr, nullptr, nullptr, nullptr, nullptr, chmaph, Cc, bCN, C6c);

    // -------- join, sp_out + fused combine, proj ----------------------------
    cudaStreamWaitEvent(0, evB, 0);
    mma_gemm<4><<<dim3(3, 32, Bb), 256, SM4>>>(gatedh, 128, b128, wb + W_SPOUT, 128, 0,
        sp_out_b, 0, nullptr, nullptr, nullptr, nullptr, 0,
        ath, chmaph, convxh, cm, nullptr, yh, Cc, bCN, 128);
    mma_gemm<4><<<dim3(32, 3, Bb), 256, SM4>>>(wb + W_PROJ, Cc, 0, yh, Cc, bCN,
        proj_b, 1, nullptr, nullptr, nullptr, nullptr, 0,
        nullptr, nullptr, nullptr, nullptr, out, nullptr, NN, bCN, Cc);
}